// round 15
// baseline (speedup 1.0000x reference)
#include <cuda_runtime.h>
#include <cuda_bf16.h>
#include <cstdint>
#include <cstddef>

#define NGn 50000
#define NDn 20000
#define HH  16384
#define EGG 800000
#define EGDA 400000
#define ELAB 200000
#define NT  (NGn + NDn + NGn)          // 120000 concat slots
#define ETOT (EGG + 2 * EGDA)          // 1600000
#define NBLK ((NT + 1023) / 1024)      // 118
#define CH  16384
#define GBg ((NGn + 127) / 128)        // 391
#define GBd ((NDn + 127) / 128)        // 157
#define EPSBN 1e-5f
#define SLOPE 0.01f
#define GEMM_SMEM (1024 + 1024 + 4 * 16384)   // 67584

#if defined(__CUDA_ARCH_FEAT_SM103_ALL) || defined(__CUDA_ARCH_FEAT_SM100_ALL)
#define TC_OK 1
#else
#define TC_OK 0
#endif

// ---------------- static device scratch ----------------
__device__ __align__(16) float d_agg_gg[(size_t)NGn * 128];
__device__ __align__(16) float d_agg_dg[(size_t)NGn * 128];
__device__ __align__(16) float d_agg_gd[(size_t)NDn * 128];
__device__ __align__(16) float d_gx[(size_t)NGn * 128];
__device__ __align__(16) float d_dx[(size_t)NDn * 128];
__device__ __align__(16) float d_g2[(size_t)NGn * 128];
__device__ __align__(16) float d_d2[(size_t)NDn * 128];
__device__ __align__(16) __nv_bfloat16 d_xgbf[(size_t)NGn * 128];   // bf16 gather copies
__device__ __align__(16) __nv_bfloat16 d_xdbf[(size_t)NDn * 128];
__device__ __align__(16) int   d_degcat[NT];
__device__ __align__(16) int   d_rowcat[NT + 1];
__device__ __align__(16) int   d_cursor[NT];
__device__ __align__(16) int   d_eidx[ETOT];
__device__ __align__(16) int   d_bsum[NBLK];
__device__ __align__(16) __nv_bfloat16 d_Bh[10 * CH];
__device__ __align__(16) __nv_bfloat16 d_Bl[10 * CH];
__device__ __align__(16) float d_Bf[10 * HH];
__device__ __align__(16) float d_cg[2 * 128];
__device__ __align__(16) float d_cd[2 * 128];
__device__ __align__(16) float d_bnacc[512];
__device__ __align__(16) float d_bnscale[256];
__device__ __align__(16) float d_bnshift[256];

// ---------------- helpers ----------------
__device__ __forceinline__ uint32_t smem_u32(const void* p) {
    uint32_t a;
    asm("{ .reg .u64 t; cvta.to.shared.u64 t, %1; cvt.u32.u64 %0, t; }" : "=r"(a) : "l"(p));
    return a;
}
__device__ __forceinline__ float4 bf2f4(uint2 u) {
    __nv_bfloat162 a = *reinterpret_cast<__nv_bfloat162*>(&u.x);
    __nv_bfloat162 b = *reinterpret_cast<__nv_bfloat162*>(&u.y);
    float2 fa = __bfloat1622float2(a), fb = __bfloat1622float2(b);
    return make_float4(fa.x, fa.y, fb.x, fb.y);
}
__device__ __forceinline__ uint2 f42bf(float4 v) {
    __nv_bfloat162 p0 = __float22bfloat162_rn(make_float2(v.x, v.y));
    __nv_bfloat162 p1 = __float22bfloat162_rn(make_float2(v.z, v.w));
    return make_uint2(*(uint32_t*)&p0, *(uint32_t*)&p1);
}
#if TC_OK
__device__ __forceinline__ uint32_t elect1() {
    uint32_t r;
    asm volatile("{ .reg .pred p; elect.sync _|p, 0xFFFFFFFF; selp.b32 %0, 1, 0, p; }" : "=r"(r));
    return r;
}
__device__ __forceinline__ uint64_t mk_desc(uint32_t addr) {
    const uint64_t base = (2ull << 61) | (1ull << 46) | (64ull << 32) | (1ull << 16);
    return base | ((uint64_t)(addr >> 4) & 0x3FFF);
}
__device__ __forceinline__ void mma_f16_ss(uint32_t d, uint64_t ad, uint64_t bd_, uint32_t idesc, bool acc) {
    uint32_t en = acc ? 1u : 0u, z = 0u;
    asm volatile(
        "{\n\t.reg .pred p;\n\tsetp.ne.u32 p, %5, 0;\n\t"
        "tcgen05.mma.cta_group::1.kind::f16 [%0], %1, %2, %3, {%4, %4, %4, %4}, p;\n\t}"
        :: "r"(d), "l"(ad), "l"(bd_), "r"(idesc), "r"(z), "r"(en) : "memory");
}
#define MBAR_WAIT(addr, ph) do {                                              \
    uint32_t _m = (addr), _p = (ph), _done;                                   \
    asm volatile("{\n\t.reg .pred p;\n\t"                                     \
        "mbarrier.try_wait.parity.acquire.cta.shared::cta.b64 p, [%1], %2;\n\t" \
        "selp.b32 %0, 1, 0, p;\n\t}" : "=r"(_done) : "r"(_m), "r"(_p) : "memory"); \
    if (!_done) {                                                             \
        asm volatile("{\n\t.reg .pred P1;\n\t"                                \
            "W%=:\n\tmbarrier.try_wait.parity.acquire.cta.shared::cta.b64 P1, [%0], %1, 0x989680;\n\t" \
            "@P1 bra.uni D%=;\n\tbra.uni W%=;\n\tD%=:\n\t}"                  \
            :: "r"(_m), "r"(_p) : "memory");                                  \
    } } while (0)

#define TC_LD_X32(r, a) asm volatile(                                         \
    "tcgen05.ld.sync.aligned.32x32b.x32.b32 "                                \
    "{%0, %1, %2, %3, %4, %5, %6, %7, %8, %9, %10, %11, %12, %13, %14, %15, "\
    " %16, %17, %18, %19, %20, %21, %22, %23, %24, %25, %26, %27, %28, %29, %30, %31}, [%32];" \
    : "=r"((r)[0]), "=r"((r)[1]), "=r"((r)[2]), "=r"((r)[3]),                 \
      "=r"((r)[4]), "=r"((r)[5]), "=r"((r)[6]), "=r"((r)[7]),                 \
      "=r"((r)[8]), "=r"((r)[9]), "=r"((r)[10]), "=r"((r)[11]),               \
      "=r"((r)[12]), "=r"((r)[13]), "=r"((r)[14]), "=r"((r)[15]),             \
      "=r"((r)[16]), "=r"((r)[17]), "=r"((r)[18]), "=r"((r)[19]),             \
      "=r"((r)[20]), "=r"((r)[21]), "=r"((r)[22]), "=r"((r)[23]),             \
      "=r"((r)[24]), "=r"((r)[25]), "=r"((r)[26]), "=r"((r)[27]),             \
      "=r"((r)[28]), "=r"((r)[29]), "=r"((r)[30]), "=r"((r)[31])              \
    : "r"(a))
#endif  // TC_OK

// ---------------- prep ----------------
__global__ void prep_w3(const float* __restrict__ Wd1, const float* __restrict__ Ws1,
                        const float* __restrict__ Wu1, const float* __restrict__ Wd2,
                        const float* __restrict__ Ws2, const float* __restrict__ Wu2,
                        __nv_bfloat16* __restrict__ Bh, __nv_bfloat16* __restrict__ Bl,
                        float* __restrict__ Bf) {
    __shared__ float red[2][128];
    int r = blockIdx.x, m = blockIdx.y, layer = blockIdx.z;
    int j = threadIdx.x & 127, kh = threadIdx.x >> 7;
    const float* Wd = layer ? Wd2 : Wd1;
    const float* Ws = layer ? Ws2 : Ws1;
    const float* Wu = layer ? Wu2 : Wu1;
    float acc = 0.f;
    int k0 = kh * 64, k1 = k0 + 64;
    if (m == 0) {
        for (int k = k0; k < k1; k++)
            acc += Wd[0 * HH + r * 128 + k] * Wu[0 * 2 * HH + k * 128 + j]
                 + Wd[2 * HH + r * 128 + k] * Wu[2 * 2 * HH + k * 128 + j];
    } else if (m == 1) {
        for (int k = k0; k < k1; k++)
            acc += Ws[0 * HH + r * 128 + k] * Wu[0 * 2 * HH + (128 + k) * 128 + j];
    } else if (m == 2) {
        for (int k = k0; k < k1; k++)
            acc += Ws[2 * HH + r * 128 + k] * Wu[2 * 2 * HH + (128 + k) * 128 + j];
    } else if (m == 3) {
        for (int k = k0; k < k1; k++)
            acc += Wd[1 * HH + r * 128 + k] * Wu[1 * 2 * HH + k * 128 + j];
    } else {
        for (int k = k0; k < k1; k++)
            acc += Ws[1 * HH + r * 128 + k] * Wu[1 * 2 * HH + (128 + k) * 128 + j];
    }
    red[kh][j] = acc;
    __syncthreads();
    if (kh == 0) {
        float v = red[0][j] + red[1][j];
        if (m < 3) v *= 0.5f;
        int cidx = layer * 5 + m;
        Bf[cidx * HH + r * 128 + j] = v;
        uint32_t byte = (uint32_t)j * 128 + (uint32_t)(r & 63) * 2;
        uint32_t swz = byte ^ ((byte >> 3) & 0x70);
        int idx = cidx * CH + (r >> 6) * 8192 + (int)(swz >> 1);
        __nv_bfloat16 h = __float2bfloat16(v);
        Bh[idx] = h;
        Bl[idx] = __float2bfloat16(v - __bfloat162float(h));
    }
}

__global__ void prep_bias3(const float* __restrict__ bd1, const float* __restrict__ bs1,
                           const float* __restrict__ bu1, const float* __restrict__ Wu1,
                           const float* __restrict__ bd2, const float* __restrict__ bs2,
                           const float* __restrict__ bu2, const float* __restrict__ Wu2) {
    __shared__ float red[4][128];
    int i = blockIdx.x, layer = blockIdx.y;
    int j = threadIdx.x & 127, kq = threadIdx.x >> 7;
    const float* bd = layer ? bd2 : bd1;
    const float* bs = layer ? bs2 : bs1;
    const float* bu = layer ? bu2 : bu1;
    const float* Wu = layer ? Wu2 : Wu1;
    float c = 0.f;
    for (int k = kq * 32; k < kq * 32 + 32; k++)
        c += bd[i * 128 + k] * Wu[i * 2 * HH + k * 128 + j]
           + bs[i * 128 + k] * Wu[i * 2 * HH + (128 + k) * 128 + j];
    red[kq][j] = c;
    __syncthreads();
    if (kq == 0) {
        float v = red[0][j] + red[1][j] + red[2][j] + red[3][j] + bu[i * 128 + j];
        if (i == 1) d_cd[layer * 128 + j] = v;
        else atomicAdd(&d_cg[layer * 128 + j], 0.5f * v);
    }
}

// ---------------- zero small scratch ----------------
__global__ void zero_misc() {
    int i = blockIdx.x * blockDim.x + threadIdx.x;
    for (int k = i; k < NT; k += gridDim.x * blockDim.x) d_degcat[k] = 0;
    if (i < 512) d_bnacc[i] = 0.f;
    if (i < 256) d_cg[i] = 0.f;
}

// ---------------- bf16 copies of layer-1 inputs (TC path only) ----------------
__global__ void conv_bf(const float* __restrict__ Xg, const float* __restrict__ Xd) {
#if TC_OK
    int idx = blockIdx.x * blockDim.x + threadIdx.x;          // quad index
    const int ng = NGn * 32;
    const int nt = ng + NDn * 32;
    if (idx >= nt) return;
    if (idx < ng) {
        float4 v = ((const float4*)Xg)[idx];
        ((uint2*)d_xgbf)[idx] = f42bf(v);
    } else {
        float4 v = ((const float4*)Xd)[idx - ng];
        ((uint2*)d_xdbf)[idx - ng] = f42bf(v);
    }
#endif
}

// ---------------- CSR build ----------------
__global__ void deg_all(const int* __restrict__ gg_dst, const int* __restrict__ gda_dst,
                        const int* __restrict__ gda_src) {
    int e = blockIdx.x * blockDim.x + threadIdx.x;
    if (e < EGG) atomicAdd(&d_degcat[gg_dst[e]], 1);
    else if (e < EGG + EGDA) atomicAdd(&d_degcat[NGn + gda_dst[e - EGG]], 1);
    else if (e < ETOT) atomicAdd(&d_degcat[NGn + NDn + gda_src[e - EGG - EGDA]], 1);
}
__global__ void scan1() {
    __shared__ int s[1024];
    int tid = threadIdx.x;
    int i = blockIdx.x * 1024 + tid;
    int v = (i < NT) ? d_degcat[i] : 0;
    s[tid] = v;
    __syncthreads();
    for (int off = 1; off < 1024; off <<= 1) {
        int t = (tid >= off) ? s[tid - off] : 0;
        __syncthreads();
        s[tid] += t;
        __syncthreads();
    }
    if (i < NT) d_rowcat[i] = s[tid] - v;
    if (tid == 1023) d_bsum[blockIdx.x] = s[1023];
}
__global__ void scan23() {
    __shared__ int s[128];
    int tid = threadIdx.x;
    if (tid < 128) s[tid] = (tid < NBLK && tid < blockIdx.x) ? d_bsum[tid] : 0;
    __syncthreads();
    for (int off = 64; off >= 1; off >>= 1) {
        if (tid < off) s[tid] += s[tid + off];
        __syncthreads();
    }
    int i = blockIdx.x * 1024 + tid;
    if (i < NT) {
        int r = d_rowcat[i] + s[0];
        d_rowcat[i] = r;
        d_cursor[i] = r;
    }
    if (blockIdx.x == 0 && tid == 0) d_rowcat[NT] = ETOT;
}
__global__ void fill_all(const int* __restrict__ gg_src, const int* __restrict__ gg_dst,
                         const int* __restrict__ gda_src, const int* __restrict__ gda_dst) {
    int e = blockIdx.x * blockDim.x + threadIdx.x;
    int v, slot;
    if (e < EGG) { v = gg_src[e]; slot = gg_dst[e]; }
    else if (e < EGG + EGDA) { int q = e - EGG; v = gda_src[q]; slot = NGn + gda_dst[q]; }
    else if (e < ETOT) { int q = e - EGG - EGDA; v = gda_dst[q]; slot = NGn + NDn + gda_src[q]; }
    else return;
    int pos = atomicAdd(&d_cursor[slot], 1);
    d_eidx[pos] = v;
}

// ---------------- merged CSR mean-gather, MLP-4; TC path reads bf16 ----------------
__global__ void gather_all(const float* __restrict__ Xg, const float* __restrict__ Xd,
                           const float* __restrict__ bnsc, const float* __restrict__ bnsh) {
    int w = (int)(((size_t)blockIdx.x * blockDim.x + threadIdx.x) >> 5);
    int lane = threadIdx.x & 31;
    if (w >= NT) return;
    float* out;
    int grp;
#if TC_OK
    const __nv_bfloat16* X;
    if (w < NGn) { X = d_xgbf; out = d_agg_gg + (size_t)w * 128; grp = 0; }
    else if (w < NGn + NDn) { X = d_xgbf; out = d_agg_gd + (size_t)(w - NGn) * 128; grp = 0; }
    else { X = d_xdbf; out = d_agg_dg + (size_t)(w - NGn - NDn) * 128; grp = 1; }
#else
    const float* X;
    if (w < NGn) { X = Xg; out = d_agg_gg + (size_t)w * 128; grp = 0; }
    else if (w < NGn + NDn) { X = Xg; out = d_agg_gd + (size_t)(w - NGn) * 128; grp = 0; }
    else { X = Xd; out = d_agg_dg + (size_t)(w - NGn - NDn) * 128; grp = 1; }
#endif
    bool bn = (bnsc != nullptr);
    float4 scv = make_float4(1.f, 1.f, 1.f, 1.f), shv = make_float4(0.f, 0.f, 0.f, 0.f);
    if (bn) {
        scv = *(const float4*)(bnsc + grp * 128 + lane * 4);
        shv = *(const float4*)(bnsh + grp * 128 + lane * 4);
    }
#if TC_OK
#define LDROW(i) bf2f4(*(const uint2*)(X + (size_t)(i) * 128 + lane * 4))
#else
#define LDROW(i) (*(const float4*)(X + (size_t)(i) * 128 + lane * 4))
#endif
#define BNT(v) do { if (bn) {                                                  \
        v.x = v.x * scv.x + shv.x; v.x = v.x >= 0.f ? v.x : SLOPE * v.x;      \
        v.y = v.y * scv.y + shv.y; v.y = v.y >= 0.f ? v.y : SLOPE * v.y;      \
        v.z = v.z * scv.z + shv.z; v.z = v.z >= 0.f ? v.z : SLOPE * v.z;      \
        v.w = v.w * scv.w + shv.w; v.w = v.w >= 0.f ? v.w : SLOPE * v.w; } } while (0)
    int start = d_rowcat[w], end = d_rowcat[w + 1];
    float4 a0 = make_float4(0.f, 0.f, 0.f, 0.f), a1 = a0, a2 = a0, a3 = a0;
    int e = start;
    int e4 = start + ((end - start) & ~3);
    for (; e < e4; e += 4) {
        int i0 = __ldg(d_eidx + e + 0);
        int i1 = __ldg(d_eidx + e + 1);
        int i2 = __ldg(d_eidx + e + 2);
        int i3 = __ldg(d_eidx + e + 3);
        float4 v0 = LDROW(i0);
        float4 v1 = LDROW(i1);
        float4 v2 = LDROW(i2);
        float4 v3 = LDROW(i3);
        BNT(v0); BNT(v1); BNT(v2); BNT(v3);
        a0.x += v0.x; a0.y += v0.y; a0.z += v0.z; a0.w += v0.w;
        a1.x += v1.x; a1.y += v1.y; a1.z += v1.z; a1.w += v1.w;
        a2.x += v2.x; a2.y += v2.y; a2.z += v2.z; a2.w += v2.w;
        a3.x += v3.x; a3.y += v3.y; a3.z += v3.z; a3.w += v3.w;
    }
    for (; e < end; e++) {
        int i0 = __ldg(d_eidx + e);
        float4 v0 = LDROW(i0);
        BNT(v0);
        a0.x += v0.x; a0.y += v0.y; a0.z += v0.z; a0.w += v0.w;
    }
#undef BNT
#undef LDROW
    float inv = 1.0f / fmaxf((float)(end - start), 1.0f);
    float4 acc;
    acc.x = (a0.x + a1.x + a2.x + a3.x) * inv;
    acc.y = (a0.y + a1.y + a2.y + a3.y) * inv;
    acc.z = (a0.z + a1.z + a2.z + a3.z) * inv;
    acc.w = (a0.w + a1.w + a2.w + a3.w) * inv;
    *(float4*)(out + lane * 4) = acc;
}

// ---------------- tcgen05 split-bf16 GEMM, k=64 panels, 3 CTAs/SM ----------------
__global__ void __launch_bounds__(256, 3)
gemm_tc_all(float* __restrict__ outG, float* __restrict__ outD,
            const float* __restrict__ gA0, const float* __restrict__ gA1,
            const float* __restrict__ gA2,
            const float* __restrict__ dA0, const float* __restrict__ dA1,
            const __nv_bfloat16* __restrict__ Bh, const __nv_bfloat16* __restrict__ Bl,
            const float* __restrict__ biasG, const float* __restrict__ biasD,
            const float* __restrict__ bnsc, const float* __restrict__ bnsh,
            __nv_bfloat16* __restrict__ obfG, __nv_bfloat16* __restrict__ obfD) {
#if TC_OK
    extern __shared__ __align__(16) char smem[];
    uint32_t raw = smem_u32(smem);
    uint32_t sb = (raw + 1023u) & ~1023u;
    char* sp = (char*)smem + (sb - raw);
    const uint32_t OAH = 1024, OAL = OAH + 16384, OBH = OAL + 16384, OBL = OBH + 16384;
    int tid = threadIdx.x, wid = tid >> 5, lane = tid & 31;

    bool gene = (blockIdx.x < GBg);
    int m0 = (gene ? blockIdx.x : blockIdx.x - GBg) * 128;
    int M = gene ? NGn : NDn;
    int nchunks = gene ? 3 : 2;
    float* out = gene ? outG : outD;
    __nv_bfloat16* obf = gene ? obfG : obfD;
    const float* bias = gene ? biasG : biasD;
    const __nv_bfloat16* BhB = Bh + (gene ? 0 : 3) * (size_t)CH;
    const __nv_bfloat16* BlB = Bl + (gene ? 0 : 3) * (size_t)CH;
    int grp = gene ? 0 : 1;

    if (wid == 0)
        asm volatile("tcgen05.alloc.cta_group::1.sync.aligned.shared::cta.b32 [%0], %1;"
                     :: "r"(sb), "r"(128) : "memory");
    if (tid == 0)
        asm volatile("mbarrier.init.shared.b64 [%0], %1;" :: "r"(sb + 8), "r"(1) : "memory");
    __syncthreads();
    uint32_t tmem;
    asm volatile("ld.shared.b32 %0, [%1];" : "=r"(tmem) : "r"(sb));
    const uint32_t idesc = 0x08200490u;

    int it = 0;
    for (int c = 0; c < nchunks; c++) {
        const float* A = gene ? ((c == 0) ? gA0 : ((c == 1) ? gA1 : gA2))
                              : ((c == 0) ? dA0 : dA1);
        bool dobn = (c == 0) && (bnsc != nullptr);
        for (int p = 0; p < 2; p++) {
            for (int i = tid; i < 2048; i += 256) {
                int row = i >> 4;
                int kq = (i & 15) << 2;
                int k4 = p * 64 + kq;
                float4 v = make_float4(0.f, 0.f, 0.f, 0.f);
                int gm = m0 + row;
                if (gm < M) {
                    v = *(const float4*)(A + (size_t)gm * 128 + k4);
                    if (dobn) {
                        float4 sc = *(const float4*)(bnsc + grp * 128 + k4);
                        float4 sh = *(const float4*)(bnsh + grp * 128 + k4);
                        v.x = v.x * sc.x + sh.x; v.x = v.x >= 0.f ? v.x : SLOPE * v.x;
                        v.y = v.y * sc.y + sh.y; v.y = v.y >= 0.f ? v.y : SLOPE * v.y;
                        v.z = v.z * sc.z + sh.z; v.z = v.z >= 0.f ? v.z : SLOPE * v.z;
                        v.w = v.w * sc.w + sh.w; v.w = v.w >= 0.f ? v.w : SLOPE * v.w;
                    }
                }
                __nv_bfloat162 h0 = __float22bfloat162_rn(make_float2(v.x, v.y));
                __nv_bfloat162 h1 = __float22bfloat162_rn(make_float2(v.z, v.w));
                float2 f0 = __bfloat1622float2(h0), f1 = __bfloat1622float2(h1);
                __nv_bfloat162 l0 = __float22bfloat162_rn(make_float2(v.x - f0.x, v.y - f0.y));
                __nv_bfloat162 l1 = __float22bfloat162_rn(make_float2(v.z - f1.x, v.w - f1.y));
                uint32_t byte = (uint32_t)row * 128 + (uint32_t)kq * 2;
                uint32_t swz = byte ^ ((byte >> 3) & 0x70);
                *(uint2*)(sp + OAH + swz) = make_uint2(*(uint32_t*)&h0, *(uint32_t*)&h1);
                *(uint2*)(sp + OAL + swz) = make_uint2(*(uint32_t*)&l0, *(uint32_t*)&l1);
            }
            for (int i = tid; i < 1024; i += 256) {
                ((float4*)(sp + OBH))[i] = ((const float4*)(BhB + (size_t)c * CH + p * 8192))[i];
                ((float4*)(sp + OBL))[i] = ((const float4*)(BlB + (size_t)c * CH + p * 8192))[i];
            }
            asm volatile("fence.proxy.async.shared::cta;" ::: "memory");
            __syncthreads();

            if (wid == 0 && elect1()) {
                for (int t = 0; t < 3; t++) {
                    uint32_t aoff = (t == 1) ? OAL : OAH;
                    uint32_t boff = (t == 2) ? OBL : OBH;
                    uint64_t ad  = mk_desc(sb + aoff);
                    uint64_t bd_ = mk_desc(sb + boff);
                    for (int s = 0; s < 4; s++)
                        mma_f16_ss(tmem, ad + s * 2, bd_ + s * 2, idesc,
                                   !(it == 0 && t == 0 && s == 0));
                }
                asm volatile("tcgen05.commit.cta_group::1.mbarrier::arrive::one.shared::cluster.b64 [%0];"
                             :: "r"(sb + 8) : "memory");
            }
            MBAR_WAIT(sb + 8, (uint32_t)(it & 1));
            __syncthreads();
            it++;
        }
    }
    asm volatile("tcgen05.fence::after_thread_sync;" ::: "memory");

    if (wid < 4) {
        int gm = m0 + wid * 32 + lane;
        for (int b = 0; b < 4; b++) {
            uint32_t r[32];
            TC_LD_X32(r, tmem + b * 32);
            asm volatile("tcgen05.wait::ld.sync.aligned;" ::: "memory");
            if (gm < M) {
#pragma unroll
                for (int q = 0; q < 8; q++) {
                    float4 o;
                    o.x = __uint_as_float(r[q * 4 + 0]) + __ldg(bias + b * 32 + q * 4 + 0);
                    o.y = __uint_as_float(r[q * 4 + 1]) + __ldg(bias + b * 32 + q * 4 + 1);
                    o.z = __uint_as_float(r[q * 4 + 2]) + __ldg(bias + b * 32 + q * 4 + 2);
                    o.w = __uint_as_float(r[q * 4 + 3]) + __ldg(bias + b * 32 + q * 4 + 3);
                    *(float4*)(out + (size_t)gm * 128 + b * 32 + q * 4) = o;
                    *(uint2*)(obf + (size_t)gm * 128 + b * 32 + q * 4) = f42bf(o);
                }
            }
        }
    }
    __syncthreads();
    if (tid == 0)
        asm volatile("mbarrier.inval.shared.b64 [%0];" :: "r"(sb + 8) : "memory");
    __syncthreads();
    if (wid == 0) {
        asm volatile("tcgen05.relinquish_alloc_permit.cta_group::1.sync.aligned;");
        asm volatile("tcgen05.dealloc.cta_group::1.sync.aligned.b32 %0, %1;" :: "r"(tmem), "r"(128));
    }
#endif  // TC_OK
}

// ---------------- SIMT fallback (base-arch cubin only) ----------------
__global__ void __launch_bounds__(256, 2)
gemm_simt_all(float* __restrict__ outG, float* __restrict__ outD,
              const float* __restrict__ gA0, const float* __restrict__ gA1,
              const float* __restrict__ gA2,
              const float* __restrict__ dA0, const float* __restrict__ dA1,
              const float* __restrict__ Bf,
              const float* __restrict__ biasG, const float* __restrict__ biasD,
              const float* __restrict__ bnsc, const float* __restrict__ bnsh) {
#if !TC_OK
    __shared__ float As[16][128];
    __shared__ float Bs[16][128];
    int tid = threadIdx.x;
    int tx = tid & 15, ty = tid >> 4;
    bool gene = (blockIdx.x < GBg);
    int m0 = (gene ? blockIdx.x : blockIdx.x - GBg) * 128;
    int M = gene ? NGn : NDn;
    int nchunks = gene ? 3 : 2;
    float* out = gene ? outG : outD;
    const float* bias = gene ? biasG : biasD;
    const float* B = Bf + (gene ? 0 : 3) * (size_t)HH;
    int grp = gene ? 0 : 1;
    float acc[8][8];
#pragma unroll
    for (int i = 0; i < 8; i++)
#pragma unroll
        for (int j = 0; j < 8; j++) acc[i][j] = 0.f;

    for (int c = 0; c < nchunks; c++) {
        const float* A = gene ? ((c == 0) ? gA0 : (c == 1) ? gA1 : gA2)
                              : ((c == 0) ? dA0 : dA1);
        bool dobn = (c == 0) && (bnsc != nullptr);
        const float* Bc = B + (size_t)c * HH;
        for (int k0 = 0; k0 < 128; k0 += 16) {
#pragma unroll
            for (int f = 0; f < 2; f++) {
                int lin = tid * 2 + f;
                int row = lin >> 2;
                int kk = (lin & 3) << 2;
                float4 v = make_float4(0.f, 0.f, 0.f, 0.f);
                int gm = m0 + row;
                if (gm < M) {
                    v = *(const float4*)(A + (size_t)gm * 128 + k0 + kk);
                    if (dobn) {
                        float4 sc = *(const float4*)(bnsc + grp * 128 + k0 + kk);
                        float4 sh = *(const float4*)(bnsh + grp * 128 + k0 + kk);
                        v.x = v.x * sc.x + sh.x; v.x = v.x >= 0.f ? v.x : SLOPE * v.x;
                        v.y = v.y * sc.y + sh.y; v.y = v.y >= 0.f ? v.y : SLOPE * v.y;
                        v.z = v.z * sc.z + sh.z; v.z = v.z >= 0.f ? v.z : SLOPE * v.z;
                        v.w = v.w * sc.w + sh.w; v.w = v.w >= 0.f ? v.w : SLOPE * v.w;
                    }
                }
                As[kk + 0][row] = v.x; As[kk + 1][row] = v.y;
                As[kk + 2][row] = v.z; As[kk + 3][row] = v.w;
                int kb = lin >> 5;
                int jb = (lin & 31) << 2;
                *(float4*)&Bs[kb][jb] = *(const float4*)(Bc + (size_t)(k0 + kb) * 128 + jb);
            }
            __syncthreads();
#pragma unroll
            for (int kk = 0; kk < 16; kk++) {
                float a[8], b[8];
#pragma unroll
                for (int i = 0; i < 8; i++) a[i] = As[kk][ty * 8 + i];
#pragma unroll
                for (int j = 0; j < 8; j++) b[j] = Bs[kk][tx * 8 + j];
#pragma unroll
                for (int i = 0; i < 8; i++)
#pragma unroll
                    for (int j = 0; j < 8; j++) acc[i][j] = fmaf(a[i], b[j], acc[i][j]);
            }
            __syncthreads();
        }
    }
    float bb[8];
#pragma unroll
    for (int j = 0; j < 8; j++) bb[j] = bias[tx * 8 + j];
#pragma unroll
    for (int i = 0; i < 8; i++) {
        int gm = m0 + ty * 8 + i;
        if (gm < M) {
#pragma unroll
            for (int j = 0; j < 8; j += 4)
                *(float4*)(out + (size_t)gm * 128 + tx * 8 + j) =
                    make_float4(acc[i][j] + bb[j], acc[i][j + 1] + bb[j + 1],
                                acc[i][j + 2] + bb[j + 2], acc[i][j + 3] + bb[j + 3]);
        }
    }
#endif  // !TC_OK
}

// ---------------- BN ----------------
__global__ void bn_stats_all() {
    __shared__ float4 s_s[8][32], s_q[8][32];
    int tid = threadIdx.x, w = tid >> 5, l = tid & 31;
    const float* X;
    float* acc;
    int M, bb, nb;
    if (blockIdx.x < 256) { X = d_gx; acc = d_bnacc; M = NGn; bb = blockIdx.x; nb = 256; }
    else { X = d_dx; acc = d_bnacc + 256; M = NDn; bb = blockIdx.x - 256; nb = 128; }
    float4 s = make_float4(0.f, 0.f, 0.f, 0.f), q = s;
    for (int r = bb * 8 + w; r < M; r += nb * 8) {
        float4 v = ((const float4*)X)[(size_t)r * 32 + l];
        s.x += v.x; s.y += v.y; s.z += v.z; s.w += v.w;
        q.x += v.x * v.x; q.y += v.y * v.y; q.z += v.z * v.z; q.w += v.w * v.w;
    }
    s_s[w][l] = s; s_q[w][l] = q;
    __syncthreads();
    if (w == 0) {
        float4 ts = s_s[0][l], tq = s_q[0][l];
        for (int ww = 1; ww < 8; ww++) {
            float4 a = s_s[ww][l], b = s_q[ww][l];
            ts.x += a.x; ts.y += a.y; ts.z += a.z; ts.w += a.w;
            tq.x += b.x; tq.y += b.y; tq.z += b.z; tq.w += b.w;
        }
        atomicAdd(&acc[l * 4 + 0], ts.x); atomicAdd(&acc[l * 4 + 1], ts.y);
        atomicAdd(&acc[l * 4 + 2], ts.z); atomicAdd(&acc[l * 4 + 3], ts.w);
        atomicAdd(&acc[128 + l * 4 + 0], tq.x); atomicAdd(&acc[128 + l * 4 + 1], tq.y);
        atomicAdd(&acc[128 + l * 4 + 2], tq.z); atomicAdd(&acc[128 + l * 4 + 3], tq.w);
    }
}
__global__ void bn_finalize(const float* __restrict__ gamma, const float* __restrict__ beta) {
    int t = threadIdx.x;
    int grp = t >> 7, j = t & 127;
    float cnt = grp ? (float)NDn : (float)NGn;
    float mean = d_bnacc[grp * 256 + j] / cnt;
    float var = d_bnacc[grp * 256 + 128 + j] / cnt - mean * mean;
    float sc = gamma[grp * 128 + j] * rsqrtf(var + EPSBN);
    d_bnscale[grp * 128 + j] = sc;
    d_bnshift[grp * 128 + j] = beta[grp * 128 + j] - mean * sc;
}

// ---------------- decoder: always fp32 final embeddings ----------------
__global__ void decoder(const int* __restrict__ ls, const int* __restrict__ ld,
                        float* __restrict__ out) {
    int w = (int)(((size_t)blockIdx.x * blockDim.x + threadIdx.x) >> 5);
    int lane = threadIdx.x & 31;
    if (w >= ELAB) return;
    int s = __ldg(ls + w), t = __ldg(ld + w);
    float4 a = *(const float4*)(d_g2 + (size_t)s * 128 + lane * 4);
    float4 b = *(const float4*)(d_d2 + (size_t)t * 128 + lane * 4);
    float p = a.x * b.x + a.y * b.y + a.z * b.z + a.w * b.w;
#pragma unroll
    for (int o = 16; o; o >>= 1) p += __shfl_xor_sync(0xffffffffu, p, o);
    if (lane == 0) out[w] = p;
}

// ---------------- host ----------------
extern "C" void kernel_launch(void* const* d_in, const int* in_sizes, int n_in,
                              void* d_out, int out_size) {
    const float* x_gene = (const float*)d_in[0];
    const float* x_dis  = (const float*)d_in[1];
    const float* Wd1 = (const float*)d_in[2];
    const float* Ws1 = (const float*)d_in[3];
    const float* Wu1 = (const float*)d_in[4];
    const float* bd1 = (const float*)d_in[5];
    const float* bs1 = (const float*)d_in[6];
    const float* bu1 = (const float*)d_in[7];
    const float* Wd2 = (const float*)d_in[8];
    const float* Ws2 = (const float*)d_in[9];
    const float* Wu2 = (const float*)d_in[10];
    const float* bd2 = (const float*)d_in[11];
    const float* bs2 = (const float*)d_in[12];
    const float* bu2 = (const float*)d_in[13];
    const float* gamma = (const float*)d_in[14];
    const float* beta  = (const float*)d_in[15];
    const int* gg_src = (const int*)d_in[16];
    const int* gg_dst = (const int*)d_in[17];
    const int* gda_src = (const int*)d_in[18];
    const int* gda_dst = (const int*)d_in[19];
    const int* ls = (const int*)d_in[20];
    const int* ld = (const int*)d_in[21];
    float* out = (float*)d_out;

    float *p_agg_gg, *p_agg_dg, *p_agg_gd, *p_gx, *p_dx, *p_g2, *p_d2;
    float *p_cg, *p_cd, *pBf, *p_bnsc, *p_bnsh;
    __nv_bfloat16 *pBh, *pBl, *p_xgbf, *p_xdbf;
    cudaGetSymbolAddress((void**)&p_agg_gg, d_agg_gg);
    cudaGetSymbolAddress((void**)&p_agg_dg, d_agg_dg);
    cudaGetSymbolAddress((void**)&p_agg_gd, d_agg_gd);
    cudaGetSymbolAddress((void**)&p_gx, d_gx);
    cudaGetSymbolAddress((void**)&p_dx, d_dx);
    cudaGetSymbolAddress((void**)&p_g2, d_g2);
    cudaGetSymbolAddress((void**)&p_d2, d_d2);
    cudaGetSymbolAddress((void**)&p_cg, d_cg);
    cudaGetSymbolAddress((void**)&p_cd, d_cd);
    cudaGetSymbolAddress((void**)&pBh, d_Bh);
    cudaGetSymbolAddress((void**)&pBl, d_Bl);
    cudaGetSymbolAddress((void**)&pBf, d_Bf);
    cudaGetSymbolAddress((void**)&p_bnsc, d_bnscale);
    cudaGetSymbolAddress((void**)&p_bnsh, d_bnshift);
    cudaGetSymbolAddress((void**)&p_xgbf, d_xgbf);
    cudaGetSymbolAddress((void**)&p_xdbf, d_xdbf);

    cudaFuncSetAttribute(gemm_tc_all, cudaFuncAttributeMaxDynamicSharedMemorySize, GEMM_SMEM);

    // prep
    zero_misc<<<512, 256>>>();
    prep_w3<<<dim3(128, 5, 2), 256>>>(Wd1, Ws1, Wu1, Wd2, Ws2, Wu2, pBh, pBl, pBf);
    prep_bias3<<<dim3(3, 2), 512>>>(bd1, bs1, bu1, Wu1, bd2, bs2, bu2, Wu2);

    // CSR build
    deg_all<<<(ETOT + 255) / 256, 256>>>(gg_dst, gda_dst, gda_src);
    scan1<<<NBLK, 1024>>>();
    scan23<<<NBLK, 1024>>>();
    fill_all<<<(ETOT + 255) / 256, 256>>>(gg_src, gg_dst, gda_src, gda_dst);

    // bf16 copies of layer-1 inputs (TC cubin only)
    conv_bf<<<((NGn + NDn) * 32 + 255) / 256, 256>>>(x_gene, x_dis);

    const int gemm_blocks = GBg + GBd;         // 548
    const int gat_blocks = (NT * 32 + 255) / 256;

    // ---- layer 1 ----
    gather_all<<<gat_blocks, 256>>>(x_gene, x_dis, nullptr, nullptr);
    gemm_tc_all<<<gemm_blocks, 256, GEMM_SMEM>>>(p_gx, p_dx, x_gene, p_agg_gg, p_agg_dg,
                                                 x_dis, p_agg_gd, pBh, pBl,
                                                 p_cg, p_cd, nullptr, nullptr,
                                                 p_xgbf, p_xdbf);
    gemm_simt_all<<<gemm_blocks, 256>>>(p_gx, p_dx, x_gene, p_agg_gg, p_agg_dg,
                                        x_dis, p_agg_gd, pBf, p_cg, p_cd, nullptr, nullptr);
    bn_stats_all<<<384, 256>>>();
    bn_finalize<<<1, 256>>>(gamma, beta);

    // ---- layer 2 (bn+lrelu applied on the fly to raw layer-1 outputs) ----
    gather_all<<<gat_blocks, 256>>>(p_gx, p_dx, p_bnsc, p_bnsh);
    gemm_tc_all<<<gemm_blocks, 256, GEMM_SMEM>>>(p_g2, p_d2, p_gx, p_agg_gg, p_agg_dg,
                                                 p_dx, p_agg_gd, pBh + 5 * CH, pBl + 5 * CH,
                                                 p_cg + 128, p_cd + 128, p_bnsc, p_bnsh,
                                                 p_xgbf, p_xdbf);
    gemm_simt_all<<<gemm_blocks, 256>>>(p_g2, p_d2, p_gx, p_agg_gg, p_agg_dg,
                                        p_dx, p_agg_gd, pBf + 5 * HH,
                                        p_cg + 128, p_cd + 128, p_bnsc, p_bnsh);

    // ---- decoder (fp32 embeddings) ----
    decoder<<<(ELAB * 32 + 255) / 256, 256>>>(ls, ld, out);
}

// round 16
// speedup vs baseline: 1.0989x; 1.0989x over previous
#include <cuda_runtime.h>
#include <cuda_bf16.h>
#include <cstdint>
#include <cstddef>

#define NGn 50000
#define NDn 20000
#define HH  16384
#define EGG 800000
#define EGDA 400000
#define ELAB 200000
#define NT  (NGn + NDn + NGn)          // 120000 concat slots
#define ETOT (EGG + 2 * EGDA)          // 1600000
#define NBLK ((NT + 1023) / 1024)      // 118
#define CH  16384                      // bf16 elems per B chunk
#define GBg ((NGn + 127) / 128)        // 391
#define GBd ((NDn + 127) / 128)        // 157
#define EPSBN 1e-5f
#define SLOPE 0.01f
#define GEMM_SMEM (1024 + 1024 + 4 * 16384)   // 67584

#if defined(__CUDA_ARCH_FEAT_SM103_ALL) || defined(__CUDA_ARCH_FEAT_SM100_ALL)
#define TC_OK 1
#else
#define TC_OK 0
#endif

// ---------------- static device scratch ----------------
__device__ __align__(16) float d_agg_gg[(size_t)NGn * 128];
__device__ __align__(16) float d_agg_dg[(size_t)NGn * 128];
__device__ __align__(16) float d_agg_gd[(size_t)NDn * 128];
__device__ __align__(16) float d_gx[(size_t)NGn * 128];
__device__ __align__(16) float d_dx[(size_t)NDn * 128];
__device__ __align__(16) float d_g2[(size_t)NGn * 128];
__device__ __align__(16) float d_d2[(size_t)NDn * 128];
__device__ __align__(16) int   d_degcat[NT];
__device__ __align__(16) int   d_rowcat[NT + 1];
__device__ __align__(16) int   d_cursor[NT];
__device__ __align__(16) int   d_eidx[ETOT];
__device__ __align__(16) int   d_bsum[NBLK];
__device__ __align__(16) __nv_bfloat16 d_Bh[10 * CH];
__device__ __align__(16) __nv_bfloat16 d_Bl[10 * CH];
__device__ __align__(16) float d_Bf[10 * HH];
__device__ __align__(16) float d_cg[2 * 128];
__device__ __align__(16) float d_cd[2 * 128];
__device__ __align__(16) float d_bnacc[512];
__device__ __align__(16) float d_bnscale[256];
__device__ __align__(16) float d_bnshift[256];

// ---------------- ptx helpers ----------------
__device__ __forceinline__ uint32_t smem_u32(const void* p) {
    uint32_t a;
    asm("{ .reg .u64 t; cvta.to.shared.u64 t, %1; cvt.u32.u64 %0, t; }" : "=r"(a) : "l"(p));
    return a;
}
#if TC_OK
__device__ __forceinline__ uint32_t elect1() {
    uint32_t r;
    asm volatile("{ .reg .pred p; elect.sync _|p, 0xFFFFFFFF; selp.b32 %0, 1, 0, p; }" : "=r"(r));
    return r;
}
__device__ __forceinline__ uint64_t mk_desc(uint32_t addr) {
    const uint64_t base = (2ull << 61) | (1ull << 46) | (64ull << 32) | (1ull << 16);
    return base | ((uint64_t)(addr >> 4) & 0x3FFF);
}
__device__ __forceinline__ void mma_f16_ss(uint32_t d, uint64_t ad, uint64_t bd_, uint32_t idesc, bool acc) {
    uint32_t en = acc ? 1u : 0u, z = 0u;
    asm volatile(
        "{\n\t.reg .pred p;\n\tsetp.ne.u32 p, %5, 0;\n\t"
        "tcgen05.mma.cta_group::1.kind::f16 [%0], %1, %2, %3, {%4, %4, %4, %4}, p;\n\t}"
        :: "r"(d), "l"(ad), "l"(bd_), "r"(idesc), "r"(z), "r"(en) : "memory");
}
#define MBAR_WAIT(addr, ph) do {                                              \
    uint32_t _m = (addr), _p = (ph), _done;                                   \
    asm volatile("{\n\t.reg .pred p;\n\t"                                     \
        "mbarrier.try_wait.parity.acquire.cta.shared::cta.b64 p, [%1], %2;\n\t" \
        "selp.b32 %0, 1, 0, p;\n\t}" : "=r"(_done) : "r"(_m), "r"(_p) : "memory"); \
    if (!_done) {                                                             \
        asm volatile("{\n\t.reg .pred P1;\n\t"                                \
            "W%=:\n\tmbarrier.try_wait.parity.acquire.cta.shared::cta.b64 P1, [%0], %1, 0x989680;\n\t" \
            "@P1 bra.uni D%=;\n\tbra.uni W%=;\n\tD%=:\n\t}"                  \
            :: "r"(_m), "r"(_p) : "memory");                                  \
    } } while (0)

#define TC_LD_X32(r, a) asm volatile(                                         \
    "tcgen05.ld.sync.aligned.32x32b.x32.b32 "                                \
    "{%0, %1, %2, %3, %4, %5, %6, %7, %8, %9, %10, %11, %12, %13, %14, %15, "\
    " %16, %17, %18, %19, %20, %21, %22, %23, %24, %25, %26, %27, %28, %29, %30, %31}, [%32];" \
    : "=r"((r)[0]), "=r"((r)[1]), "=r"((r)[2]), "=r"((r)[3]),                 \
      "=r"((r)[4]), "=r"((r)[5]), "=r"((r)[6]), "=r"((r)[7]),                 \
      "=r"((r)[8]), "=r"((r)[9]), "=r"((r)[10]), "=r"((r)[11]),               \
      "=r"((r)[12]), "=r"((r)[13]), "=r"((r)[14]), "=r"((r)[15]),             \
      "=r"((r)[16]), "=r"((r)[17]), "=r"((r)[18]), "=r"((r)[19]),             \
      "=r"((r)[20]), "=r"((r)[21]), "=r"((r)[22]), "=r"((r)[23]),             \
      "=r"((r)[24]), "=r"((r)[25]), "=r"((r)[26]), "=r"((r)[27]),             \
      "=r"((r)[28]), "=r"((r)[29]), "=r"((r)[30]), "=r"((r)[31])              \
    : "r"(a))
#endif  // TC_OK

// ---------------- prep (also zeroes small scratch; ordered before consumers) ----------------
__global__ void prep_w3(const float* __restrict__ Wd1, const float* __restrict__ Ws1,
                        const float* __restrict__ Wu1, const float* __restrict__ Wd2,
                        const float* __restrict__ Ws2, const float* __restrict__ Wu2,
                        __nv_bfloat16* __restrict__ Bh, __nv_bfloat16* __restrict__ Bl,
                        float* __restrict__ Bf) {
    // zeroing preamble (replaces zero_misc launch)
    {
        int lb = (blockIdx.z * 5 + blockIdx.y) * 128 + blockIdx.x;   // 0..1279
        int gtid = lb * 256 + threadIdx.x;
        int total = gridDim.x * gridDim.y * gridDim.z * 256;
        for (int k = gtid; k < NT; k += total) d_degcat[k] = 0;
        if (gtid < 512) d_bnacc[gtid] = 0.f;
        if (gtid < 256) d_cg[gtid] = 0.f;
    }
    __shared__ float red[2][128];
    int r = blockIdx.x, m = blockIdx.y, layer = blockIdx.z;
    int j = threadIdx.x & 127, kh = threadIdx.x >> 7;
    const float* Wd = layer ? Wd2 : Wd1;
    const float* Ws = layer ? Ws2 : Ws1;
    const float* Wu = layer ? Wu2 : Wu1;
    float acc = 0.f;
    int k0 = kh * 64, k1 = k0 + 64;
    if (m == 0) {
        for (int k = k0; k < k1; k++)
            acc += Wd[0 * HH + r * 128 + k] * Wu[0 * 2 * HH + k * 128 + j]
                 + Wd[2 * HH + r * 128 + k] * Wu[2 * 2 * HH + k * 128 + j];
    } else if (m == 1) {
        for (int k = k0; k < k1; k++)
            acc += Ws[0 * HH + r * 128 + k] * Wu[0 * 2 * HH + (128 + k) * 128 + j];
    } else if (m == 2) {
        for (int k = k0; k < k1; k++)
            acc += Ws[2 * HH + r * 128 + k] * Wu[2 * 2 * HH + (128 + k) * 128 + j];
    } else if (m == 3) {
        for (int k = k0; k < k1; k++)
            acc += Wd[1 * HH + r * 128 + k] * Wu[1 * 2 * HH + k * 128 + j];
    } else {
        for (int k = k0; k < k1; k++)
            acc += Ws[1 * HH + r * 128 + k] * Wu[1 * 2 * HH + (128 + k) * 128 + j];
    }
    red[kh][j] = acc;
    __syncthreads();
    if (kh == 0) {
        float v = red[0][j] + red[1][j];
        if (m < 3) v *= 0.5f;
        int cidx = layer * 5 + m;
        Bf[cidx * HH + r * 128 + j] = v;
        uint32_t byte = (uint32_t)j * 128 + (uint32_t)(r & 63) * 2;
        uint32_t swz = byte ^ ((byte >> 3) & 0x70);
        int idx = cidx * CH + (r >> 6) * 8192 + (int)(swz >> 1);
        __nv_bfloat16 h = __float2bfloat16(v);
        Bh[idx] = h;
        Bl[idx] = __float2bfloat16(v - __bfloat162float(h));
    }
}

__global__ void prep_bias3(const float* __restrict__ bd1, const float* __restrict__ bs1,
                           const float* __restrict__ bu1, const float* __restrict__ Wu1,
                           const float* __restrict__ bd2, const float* __restrict__ bs2,
                           const float* __restrict__ bu2, const float* __restrict__ Wu2) {
    __shared__ float red[4][128];
    int i = blockIdx.x, layer = blockIdx.y;
    int j = threadIdx.x & 127, kq = threadIdx.x >> 7;
    const float* bd = layer ? bd2 : bd1;
    const float* bs = layer ? bs2 : bs1;
    const float* bu = layer ? bu2 : bu1;
    const float* Wu = layer ? Wu2 : Wu1;
    float c = 0.f;
    for (int k = kq * 32; k < kq * 32 + 32; k++)
        c += bd[i * 128 + k] * Wu[i * 2 * HH + k * 128 + j]
           + bs[i * 128 + k] * Wu[i * 2 * HH + (128 + k) * 128 + j];
    red[kq][j] = c;
    __syncthreads();
    if (kq == 0) {
        float v = red[0][j] + red[1][j] + red[2][j] + red[3][j] + bu[i * 128 + j];
        if (i == 1) d_cd[layer * 128 + j] = v;
        else atomicAdd(&d_cg[layer * 128 + j], 0.5f * v);
    }
}

// ---------------- CSR build ----------------
__global__ void deg_all(const int* __restrict__ gg_dst, const int* __restrict__ gda_dst,
                        const int* __restrict__ gda_src) {
    int e = blockIdx.x * blockDim.x + threadIdx.x;
    if (e < EGG) atomicAdd(&d_degcat[gg_dst[e]], 1);
    else if (e < EGG + EGDA) atomicAdd(&d_degcat[NGn + gda_dst[e - EGG]], 1);
    else if (e < ETOT) atomicAdd(&d_degcat[NGn + NDn + gda_src[e - EGG - EGDA]], 1);
}
__global__ void scan1() {
    __shared__ int s[1024];
    int tid = threadIdx.x;
    int i = blockIdx.x * 1024 + tid;
    int v = (i < NT) ? d_degcat[i] : 0;
    s[tid] = v;
    __syncthreads();
    for (int off = 1; off < 1024; off <<= 1) {
        int t = (tid >= off) ? s[tid - off] : 0;
        __syncthreads();
        s[tid] += t;
        __syncthreads();
    }
    if (i < NT) d_rowcat[i] = s[tid] - v;
    if (tid == 1023) d_bsum[blockIdx.x] = s[1023];
}
__global__ void scan23() {
    __shared__ int s[128];
    int tid = threadIdx.x;
    if (tid < 128) s[tid] = (tid < NBLK && tid < blockIdx.x) ? d_bsum[tid] : 0;
    __syncthreads();
    for (int off = 64; off >= 1; off >>= 1) {
        if (tid < off) s[tid] += s[tid + off];
        __syncthreads();
    }
    int i = blockIdx.x * 1024 + tid;
    if (i < NT) {
        int r = d_rowcat[i] + s[0];
        d_rowcat[i] = r;
        d_cursor[i] = r;
    }
    if (blockIdx.x == 0 && tid == 0) d_rowcat[NT] = ETOT;
}
__global__ void fill_all(const int* __restrict__ gg_src, const int* __restrict__ gg_dst,
                         const int* __restrict__ gda_src, const int* __restrict__ gda_dst) {
    int e = blockIdx.x * blockDim.x + threadIdx.x;
    int v, slot;
    if (e < EGG) { v = gg_src[e]; slot = gg_dst[e]; }
    else if (e < EGG + EGDA) { int q = e - EGG; v = gda_src[q]; slot = NGn + gda_dst[q]; }
    else if (e < ETOT) { int q = e - EGG - EGDA; v = gda_dst[q]; slot = NGn + NDn + gda_src[q]; }
    else return;
    int pos = atomicAdd(&d_cursor[slot], 1);
    d_eidx[pos] = v;
}

// ---------------- merged CSR mean-gather, MLP-4 x unroll-2 ----------------
__global__ void gather_all(const float* __restrict__ Xg, const float* __restrict__ Xd,
                           const float* __restrict__ bnsc, const float* __restrict__ bnsh) {
    int w = (int)(((size_t)blockIdx.x * blockDim.x + threadIdx.x) >> 5);
    int lane = threadIdx.x & 31;
    if (w >= NT) return;
    const float* X;
    float* out;
    int grp;
    if (w < NGn) { X = Xg; out = d_agg_gg + (size_t)w * 128; grp = 0; }
    else if (w < NGn + NDn) { X = Xg; out = d_agg_gd + (size_t)(w - NGn) * 128; grp = 0; }
    else { X = Xd; out = d_agg_dg + (size_t)(w - NGn - NDn) * 128; grp = 1; }
    bool bn = (bnsc != nullptr);
    float4 scv = make_float4(1.f, 1.f, 1.f, 1.f), shv = make_float4(0.f, 0.f, 0.f, 0.f);
    if (bn) {
        scv = *(const float4*)(bnsc + grp * 128 + lane * 4);
        shv = *(const float4*)(bnsh + grp * 128 + lane * 4);
    }
#define BNT(v) do { if (bn) {                                                  \
        v.x = v.x * scv.x + shv.x; v.x = v.x >= 0.f ? v.x : SLOPE * v.x;      \
        v.y = v.y * scv.y + shv.y; v.y = v.y >= 0.f ? v.y : SLOPE * v.y;      \
        v.z = v.z * scv.z + shv.z; v.z = v.z >= 0.f ? v.z : SLOPE * v.z;      \
        v.w = v.w * scv.w + shv.w; v.w = v.w >= 0.f ? v.w : SLOPE * v.w; } } while (0)
    int start = d_rowcat[w], end = d_rowcat[w + 1];
    float4 a0 = make_float4(0.f, 0.f, 0.f, 0.f), a1 = a0, a2 = a0, a3 = a0;
    int e = start;
    int e4 = start + ((end - start) & ~3);
#pragma unroll 2
    for (; e < e4; e += 4) {
        int i0 = __ldg(d_eidx + e + 0);
        int i1 = __ldg(d_eidx + e + 1);
        int i2 = __ldg(d_eidx + e + 2);
        int i3 = __ldg(d_eidx + e + 3);
        float4 v0 = *(const float4*)(X + (size_t)i0 * 128 + lane * 4);
        float4 v1 = *(const float4*)(X + (size_t)i1 * 128 + lane * 4);
        float4 v2 = *(const float4*)(X + (size_t)i2 * 128 + lane * 4);
        float4 v3 = *(const float4*)(X + (size_t)i3 * 128 + lane * 4);
        BNT(v0); BNT(v1); BNT(v2); BNT(v3);
        a0.x += v0.x; a0.y += v0.y; a0.z += v0.z; a0.w += v0.w;
        a1.x += v1.x; a1.y += v1.y; a1.z += v1.z; a1.w += v1.w;
        a2.x += v2.x; a2.y += v2.y; a2.z += v2.z; a2.w += v2.w;
        a3.x += v3.x; a3.y += v3.y; a3.z += v3.z; a3.w += v3.w;
    }
    for (; e < end; e++) {
        int i0 = __ldg(d_eidx + e);
        float4 v0 = *(const float4*)(X + (size_t)i0 * 128 + lane * 4);
        BNT(v0);
        a0.x += v0.x; a0.y += v0.y; a0.z += v0.z; a0.w += v0.w;
    }
#undef BNT
    float inv = 1.0f / fmaxf((float)(end - start), 1.0f);
    float4 acc;
    acc.x = (a0.x + a1.x + a2.x + a3.x) * inv;
    acc.y = (a0.y + a1.y + a2.y + a3.y) * inv;
    acc.z = (a0.z + a1.z + a2.z + a3.z) * inv;
    acc.w = (a0.w + a1.w + a2.w + a3.w) * inv;
    *(float4*)(out + lane * 4) = acc;
}

// ---------------- tcgen05 split-bf16 GEMM, k=64 panels, 3 CTAs/SM ----------------
__global__ void __launch_bounds__(256, 3)
gemm_tc_all(float* __restrict__ outG, float* __restrict__ outD,
            const float* __restrict__ gA0, const float* __restrict__ gA1,
            const float* __restrict__ gA2,
            const float* __restrict__ dA0, const float* __restrict__ dA1,
            const __nv_bfloat16* __restrict__ Bh, const __nv_bfloat16* __restrict__ Bl,
            const float* __restrict__ biasG, const float* __restrict__ biasD,
            const float* __restrict__ bnsc, const float* __restrict__ bnsh) {
#if TC_OK
    extern __shared__ __align__(16) char smem[];
    uint32_t raw = smem_u32(smem);
    uint32_t sb = (raw + 1023u) & ~1023u;
    char* sp = (char*)smem + (sb - raw);
    const uint32_t OAH = 1024, OAL = OAH + 16384, OBH = OAL + 16384, OBL = OBH + 16384;
    int tid = threadIdx.x, wid = tid >> 5, lane = tid & 31;

    bool gene = (blockIdx.x < GBg);
    int m0 = (gene ? blockIdx.x : blockIdx.x - GBg) * 128;
    int M = gene ? NGn : NDn;
    int nchunks = gene ? 3 : 2;
    float* out = gene ? outG : outD;
    const float* bias = gene ? biasG : biasD;
    const __nv_bfloat16* BhB = Bh + (gene ? 0 : 3) * (size_t)CH;
    const __nv_bfloat16* BlB = Bl + (gene ? 0 : 3) * (size_t)CH;
    int grp = gene ? 0 : 1;

    if (wid == 0)
        asm volatile("tcgen05.alloc.cta_group::1.sync.aligned.shared::cta.b32 [%0], %1;"
                     :: "r"(sb), "r"(128) : "memory");
    if (tid == 0)
        asm volatile("mbarrier.init.shared.b64 [%0], %1;" :: "r"(sb + 8), "r"(1) : "memory");
    __syncthreads();
    uint32_t tmem;
    asm volatile("ld.shared.b32 %0, [%1];" : "=r"(tmem) : "r"(sb));
    const uint32_t idesc = 0x08200490u;

    int it = 0;
    for (int c = 0; c < nchunks; c++) {
        const float* A = gene ? ((c == 0) ? gA0 : ((c == 1) ? gA1 : gA2))
                              : ((c == 0) ? dA0 : dA1);
        bool dobn = (c == 0) && (bnsc != nullptr);
        for (int p = 0; p < 2; p++) {
            for (int i = tid; i < 2048; i += 256) {
                int row = i >> 4;
                int kq = (i & 15) << 2;
                int k4 = p * 64 + kq;
                float4 v = make_float4(0.f, 0.f, 0.f, 0.f);
                int gm = m0 + row;
                if (gm < M) {
                    v = *(const float4*)(A + (size_t)gm * 128 + k4);
                    if (dobn) {
                        float4 sc = *(const float4*)(bnsc + grp * 128 + k4);
                        float4 sh = *(const float4*)(bnsh + grp * 128 + k4);
                        v.x = v.x * sc.x + sh.x; v.x = v.x >= 0.f ? v.x : SLOPE * v.x;
                        v.y = v.y * sc.y + sh.y; v.y = v.y >= 0.f ? v.y : SLOPE * v.y;
                        v.z = v.z * sc.z + sh.z; v.z = v.z >= 0.f ? v.z : SLOPE * v.z;
                        v.w = v.w * sc.w + sh.w; v.w = v.w >= 0.f ? v.w : SLOPE * v.w;
                    }
                }
                __nv_bfloat162 h0 = __float22bfloat162_rn(make_float2(v.x, v.y));
                __nv_bfloat162 h1 = __float22bfloat162_rn(make_float2(v.z, v.w));
                float2 f0 = __bfloat1622float2(h0), f1 = __bfloat1622float2(h1);
                __nv_bfloat162 l0 = __float22bfloat162_rn(make_float2(v.x - f0.x, v.y - f0.y));
                __nv_bfloat162 l1 = __float22bfloat162_rn(make_float2(v.z - f1.x, v.w - f1.y));
                uint32_t byte = (uint32_t)row * 128 + (uint32_t)kq * 2;
                uint32_t swz = byte ^ ((byte >> 3) & 0x70);
                *(uint2*)(sp + OAH + swz) = make_uint2(*(uint32_t*)&h0, *(uint32_t*)&h1);
                *(uint2*)(sp + OAL + swz) = make_uint2(*(uint32_t*)&l0, *(uint32_t*)&l1);
            }
            for (int i = tid; i < 1024; i += 256) {
                ((float4*)(sp + OBH))[i] = ((const float4*)(BhB + (size_t)c * CH + p * 8192))[i];
                ((float4*)(sp + OBL))[i] = ((const float4*)(BlB + (size_t)c * CH + p * 8192))[i];
            }
            asm volatile("fence.proxy.async.shared::cta;" ::: "memory");
            __syncthreads();

            if (wid == 0 && elect1()) {
                for (int t = 0; t < 3; t++) {
                    uint32_t aoff = (t == 1) ? OAL : OAH;
                    uint32_t boff = (t == 2) ? OBL : OBH;
                    uint64_t ad  = mk_desc(sb + aoff);
                    uint64_t bd_ = mk_desc(sb + boff);
                    for (int s = 0; s < 4; s++)
                        mma_f16_ss(tmem, ad + s * 2, bd_ + s * 2, idesc,
                                   !(it == 0 && t == 0 && s == 0));
                }
                asm volatile("tcgen05.commit.cta_group::1.mbarrier::arrive::one.shared::cluster.b64 [%0];"
                             :: "r"(sb + 8) : "memory");
            }
            MBAR_WAIT(sb + 8, (uint32_t)(it & 1));
            __syncthreads();
            it++;
        }
    }
    asm volatile("tcgen05.fence::after_thread_sync;" ::: "memory");

    if (wid < 4) {
        int gm = m0 + wid * 32 + lane;
        for (int b = 0; b < 4; b++) {
            uint32_t r[32];
            TC_LD_X32(r, tmem + b * 32);
            asm volatile("tcgen05.wait::ld.sync.aligned;" ::: "memory");
            if (gm < M) {
#pragma unroll
                for (int q = 0; q < 8; q++) {
                    float4 o;
                    o.x = __uint_as_float(r[q * 4 + 0]) + __ldg(bias + b * 32 + q * 4 + 0);
                    o.y = __uint_as_float(r[q * 4 + 1]) + __ldg(bias + b * 32 + q * 4 + 1);
                    o.z = __uint_as_float(r[q * 4 + 2]) + __ldg(bias + b * 32 + q * 4 + 2);
                    o.w = __uint_as_float(r[q * 4 + 3]) + __ldg(bias + b * 32 + q * 4 + 3);
                    *(float4*)(out + (size_t)gm * 128 + b * 32 + q * 4) = o;
                }
            }
        }
    }
    __syncthreads();
    if (tid == 0)
        asm volatile("mbarrier.inval.shared.b64 [%0];" :: "r"(sb + 8) : "memory");
    __syncthreads();
    if (wid == 0) {
        asm volatile("tcgen05.relinquish_alloc_permit.cta_group::1.sync.aligned;");
        asm volatile("tcgen05.dealloc.cta_group::1.sync.aligned.b32 %0, %1;" :: "r"(tmem), "r"(128));
    }
#endif  // TC_OK
}

// ---------------- SIMT fallback (base-arch cubin only) ----------------
__global__ void __launch_bounds__(256, 2)
gemm_simt_all(float* __restrict__ outG, float* __restrict__ outD,
              const float* __restrict__ gA0, const float* __restrict__ gA1,
              const float* __restrict__ gA2,
              const float* __restrict__ dA0, const float* __restrict__ dA1,
              const float* __restrict__ Bf,
              const float* __restrict__ biasG, const float* __restrict__ biasD,
              const float* __restrict__ bnsc, const float* __restrict__ bnsh) {
#if !TC_OK
    __shared__ float As[16][128];
    __shared__ float Bs[16][128];
    int tid = threadIdx.x;
    int tx = tid & 15, ty = tid >> 4;
    bool gene = (blockIdx.x < GBg);
    int m0 = (gene ? blockIdx.x : blockIdx.x - GBg) * 128;
    int M = gene ? NGn : NDn;
    int nchunks = gene ? 3 : 2;
    float* out = gene ? outG : outD;
    const float* bias = gene ? biasG : biasD;
    const float* B = Bf + (gene ? 0 : 3) * (size_t)HH;
    int grp = gene ? 0 : 1;
    float acc[8][8];
#pragma unroll
    for (int i = 0; i < 8; i++)
#pragma unroll
        for (int j = 0; j < 8; j++) acc[i][j] = 0.f;

    for (int c = 0; c < nchunks; c++) {
        const float* A = gene ? ((c == 0) ? gA0 : (c == 1) ? gA1 : gA2)
                              : ((c == 0) ? dA0 : dA1);
        bool dobn = (c == 0) && (bnsc != nullptr);
        const float* Bc = B + (size_t)c * HH;
        for (int k0 = 0; k0 < 128; k0 += 16) {
#pragma unroll
            for (int f = 0; f < 2; f++) {
                int lin = tid * 2 + f;
                int row = lin >> 2;
                int kk = (lin & 3) << 2;
                float4 v = make_float4(0.f, 0.f, 0.f, 0.f);
                int gm = m0 + row;
                if (gm < M) {
                    v = *(const float4*)(A + (size_t)gm * 128 + k0 + kk);
                    if (dobn) {
                        float4 sc = *(const float4*)(bnsc + grp * 128 + k0 + kk);
                        float4 sh = *(const float4*)(bnsh + grp * 128 + k0 + kk);
                        v.x = v.x * sc.x + sh.x; v.x = v.x >= 0.f ? v.x : SLOPE * v.x;
                        v.y = v.y * sc.y + sh.y; v.y = v.y >= 0.f ? v.y : SLOPE * v.y;
                        v.z = v.z * sc.z + sh.z; v.z = v.z >= 0.f ? v.z : SLOPE * v.z;
                        v.w = v.w * sc.w + sh.w; v.w = v.w >= 0.f ? v.w : SLOPE * v.w;
                    }
                }
                As[kk + 0][row] = v.x; As[kk + 1][row] = v.y;
                As[kk + 2][row] = v.z; As[kk + 3][row] = v.w;
                int kb = lin >> 5;
                int jb = (lin & 31) << 2;
                *(float4*)&Bs[kb][jb] = *(const float4*)(Bc + (size_t)(k0 + kb) * 128 + jb);
            }
            __syncthreads();
#pragma unroll
            for (int kk = 0; kk < 16; kk++) {
                float a[8], b[8];
#pragma unroll
                for (int i = 0; i < 8; i++) a[i] = As[kk][ty * 8 + i];
#pragma unroll
                for (int j = 0; j < 8; j++) b[j] = Bs[kk][tx * 8 + j];
#pragma unroll
                for (int i = 0; i < 8; i++)
#pragma unroll
                    for (int j = 0; j < 8; j++) acc[i][j] = fmaf(a[i], b[j], acc[i][j]);
            }
            __syncthreads();
        }
    }
    float bb[8];
#pragma unroll
    for (int j = 0; j < 8; j++) bb[j] = bias[tx * 8 + j];
#pragma unroll
    for (int i = 0; i < 8; i++) {
        int gm = m0 + ty * 8 + i;
        if (gm < M) {
#pragma unroll
            for (int j = 0; j < 8; j += 4)
                *(float4*)(out + (size_t)gm * 128 + tx * 8 + j) =
                    make_float4(acc[i][j] + bb[j], acc[i][j + 1] + bb[j + 1],
                                acc[i][j + 2] + bb[j + 2], acc[i][j + 3] + bb[j + 3]);
        }
    }
#endif  // !TC_OK
}

// ---------------- BN ----------------
__global__ void bn_stats_all() {
    __shared__ float4 s_s[8][32], s_q[8][32];
    int tid = threadIdx.x, w = tid >> 5, l = tid & 31;
    const float* X;
    float* acc;
    int M, bb, nb;
    if (blockIdx.x < 256) { X = d_gx; acc = d_bnacc; M = NGn; bb = blockIdx.x; nb = 256; }
    else { X = d_dx; acc = d_bnacc + 256; M = NDn; bb = blockIdx.x - 256; nb = 128; }
    float4 s = make_float4(0.f, 0.f, 0.f, 0.f), q = s;
    for (int r = bb * 8 + w; r < M; r += nb * 8) {
        float4 v = ((const float4*)X)[(size_t)r * 32 + l];
        s.x += v.x; s.y += v.y; s.z += v.z; s.w += v.w;
        q.x += v.x * v.x; q.y += v.y * v.y; q.z += v.z * v.z; q.w += v.w * v.w;
    }
    s_s[w][l] = s; s_q[w][l] = q;
    __syncthreads();
    if (w == 0) {
        float4 ts = s_s[0][l], tq = s_q[0][l];
        for (int ww = 1; ww < 8; ww++) {
            float4 a = s_s[ww][l], b = s_q[ww][l];
            ts.x += a.x; ts.y += a.y; ts.z += a.z; ts.w += a.w;
            tq.x += b.x; tq.y += b.y; tq.z += b.z; tq.w += b.w;
        }
        atomicAdd(&acc[l * 4 + 0], ts.x); atomicAdd(&acc[l * 4 + 1], ts.y);
        atomicAdd(&acc[l * 4 + 2], ts.z); atomicAdd(&acc[l * 4 + 3], ts.w);
        atomicAdd(&acc[128 + l * 4 + 0], tq.x); atomicAdd(&acc[128 + l * 4 + 1], tq.y);
        atomicAdd(&acc[128 + l * 4 + 2], tq.z); atomicAdd(&acc[128 + l * 4 + 3], tq.w);
    }
}
__global__ void bn_finalize(const float* __restrict__ gamma, const float* __restrict__ beta) {
    int t = threadIdx.x;
    int grp = t >> 7, j = t & 127;
    float cnt = grp ? (float)NDn : (float)NGn;
    float mean = d_bnacc[grp * 256 + j] / cnt;
    float var = d_bnacc[grp * 256 + 128 + j] / cnt - mean * mean;
    float sc = gamma[grp * 128 + j] * rsqrtf(var + EPSBN);
    d_bnscale[grp * 128 + j] = sc;
    d_bnshift[grp * 128 + j] = beta[grp * 128 + j] - mean * sc;
}

// ---------------- decoder ----------------
__global__ void decoder(const int* __restrict__ ls, const int* __restrict__ ld,
                        float* __restrict__ out) {
    int w = (int)(((size_t)blockIdx.x * blockDim.x + threadIdx.x) >> 5);
    int lane = threadIdx.x & 31;
    if (w >= ELAB) return;
    int s = __ldg(ls + w), t = __ldg(ld + w);
    float4 a = *(const float4*)(d_g2 + (size_t)s * 128 + lane * 4);
    float4 b = *(const float4*)(d_d2 + (size_t)t * 128 + lane * 4);
    float p = a.x * b.x + a.y * b.y + a.z * b.z + a.w * b.w;
#pragma unroll
    for (int o = 16; o; o >>= 1) p += __shfl_xor_sync(0xffffffffu, p, o);
    if (lane == 0) out[w] = p;
}

// ---------------- host ----------------
extern "C" void kernel_launch(void* const* d_in, const int* in_sizes, int n_in,
                              void* d_out, int out_size) {
    const float* x_gene = (const float*)d_in[0];
    const float* x_dis  = (const float*)d_in[1];
    const float* Wd1 = (const float*)d_in[2];
    const float* Ws1 = (const float*)d_in[3];
    const float* Wu1 = (const float*)d_in[4];
    const float* bd1 = (const float*)d_in[5];
    const float* bs1 = (const float*)d_in[6];
    const float* bu1 = (const float*)d_in[7];
    const float* Wd2 = (const float*)d_in[8];
    const float* Ws2 = (const float*)d_in[9];
    const float* Wu2 = (const float*)d_in[10];
    const float* bd2 = (const float*)d_in[11];
    const float* bs2 = (const float*)d_in[12];
    const float* bu2 = (const float*)d_in[13];
    const float* gamma = (const float*)d_in[14];
    const float* beta  = (const float*)d_in[15];
    const int* gg_src = (const int*)d_in[16];
    const int* gg_dst = (const int*)d_in[17];
    const int* gda_src = (const int*)d_in[18];
    const int* gda_dst = (const int*)d_in[19];
    const int* ls = (const int*)d_in[20];
    const int* ld = (const int*)d_in[21];
    float* out = (float*)d_out;

    float *p_agg_gg, *p_agg_dg, *p_agg_gd, *p_gx, *p_dx, *p_g2, *p_d2;
    float *p_cg, *p_cd, *pBf, *p_bnsc, *p_bnsh;
    __nv_bfloat16 *pBh, *pBl;
    cudaGetSymbolAddress((void**)&p_agg_gg, d_agg_gg);
    cudaGetSymbolAddress((void**)&p_agg_dg, d_agg_dg);
    cudaGetSymbolAddress((void**)&p_agg_gd, d_agg_gd);
    cudaGetSymbolAddress((void**)&p_gx, d_gx);
    cudaGetSymbolAddress((void**)&p_dx, d_dx);
    cudaGetSymbolAddress((void**)&p_g2, d_g2);
    cudaGetSymbolAddress((void**)&p_d2, d_d2);
    cudaGetSymbolAddress((void**)&p_cg, d_cg);
    cudaGetSymbolAddress((void**)&p_cd, d_cd);
    cudaGetSymbolAddress((void**)&pBh, d_Bh);
    cudaGetSymbolAddress((void**)&pBl, d_Bl);
    cudaGetSymbolAddress((void**)&pBf, d_Bf);
    cudaGetSymbolAddress((void**)&p_bnsc, d_bnscale);
    cudaGetSymbolAddress((void**)&p_bnsh, d_bnshift);

    cudaFuncSetAttribute(gemm_tc_all, cudaFuncAttributeMaxDynamicSharedMemorySize, GEMM_SMEM);

    // prep (includes scratch zeroing)
    prep_w3<<<dim3(128, 5, 2), 256>>>(Wd1, Ws1, Wu1, Wd2, Ws2, Wu2, pBh, pBl, pBf);
    prep_bias3<<<dim3(3, 2), 512>>>(bd1, bs1, bu1, Wu1, bd2, bs2, bu2, Wu2);

    // CSR build
    deg_all<<<(ETOT + 255) / 256, 256>>>(gg_dst, gda_dst, gda_src);
    scan1<<<NBLK, 1024>>>();
    scan23<<<NBLK, 1024>>>();
    fill_all<<<(ETOT + 255) / 256, 256>>>(gg_src, gg_dst, gda_src, gda_dst);

    const int gemm_blocks = GBg + GBd;         // 548
    const int gat_blocks = (NT * 32 + 255) / 256;

    // ---- layer 1 ----
    gather_all<<<gat_blocks, 256>>>(x_gene, x_dis, nullptr, nullptr);
    gemm_tc_all<<<gemm_blocks, 256, GEMM_SMEM>>>(p_gx, p_dx, x_gene, p_agg_gg, p_agg_dg,
                                                 x_dis, p_agg_gd, pBh, pBl,
                                                 p_cg, p_cd, nullptr, nullptr);
    gemm_simt_all<<<gemm_blocks, 256>>>(p_gx, p_dx, x_gene, p_agg_gg, p_agg_dg,
                                        x_dis, p_agg_gd, pBf, p_cg, p_cd, nullptr, nullptr);
    bn_stats_all<<<384, 256>>>();
    bn_finalize<<<1, 256>>>(gamma, beta);

    // ---- layer 2 (bn+lrelu applied on the fly) ----
    gather_all<<<gat_blocks, 256>>>(p_gx, p_dx, p_bnsc, p_bnsh);
    gemm_tc_all<<<gemm_blocks, 256, GEMM_SMEM>>>(p_g2, p_d2, p_gx, p_agg_gg, p_agg_dg,
                                                 p_dx, p_agg_gd, pBh + 5 * CH, pBl + 5 * CH,
                                                 p_cg + 128, p_cd + 128, p_bnsc, p_bnsh);
    gemm_simt_all<<<gemm_blocks, 256>>>(p_g2, p_d2, p_gx, p_agg_gg, p_agg_dg,
                                        p_dx, p_agg_gd, pBf + 5 * HH,
                                        p_cg + 128, p_cd + 128, p_bnsc, p_bnsh);

    // ---- decoder ----
    decoder<<<(ELAB * 32 + 255) / 256, 256>>>(ls, ld, out);
}

// round 17
// speedup vs baseline: 1.2189x; 1.1092x over previous
#include <cuda_runtime.h>
#include <cuda_bf16.h>
#include <cstdint>
#include <cstddef>

#define NGn 50000
#define NDn 20000
#define HH  16384
#define EGG 800000
#define EGDA 400000
#define ELAB 200000
#define NT  (NGn + NDn + NGn)          // 120000 concat slots
#define ETOT (EGG + 2 * EGDA)          // 1600000
#define NBLK ((NT + 1023) / 1024)      // 118
#define CH  16384                      // bf16 elems per B chunk
#define GBg ((NGn + 127) / 128)        // 391
#define GBd ((NDn + 127) / 128)        // 157
#define PBLK 1184                      // persistent grid: 148 SMs x 8 blocks
#define EPSBN 1e-5f
#define SLOPE 0.01f
#define GEMM_SMEM (1024 + 1024 + 4 * 16384)   // 67584

#if defined(__CUDA_ARCH_FEAT_SM103_ALL) || defined(__CUDA_ARCH_FEAT_SM100_ALL)
#define TC_OK 1
#else
#define TC_OK 0
#endif

// ---------------- static device scratch ----------------
__device__ __align__(16) float d_agg_gg[(size_t)NGn * 128];
__device__ __align__(16) float d_agg_dg[(size_t)NGn * 128];
__device__ __align__(16) float d_agg_gd[(size_t)NDn * 128];
__device__ __align__(16) float d_gx[(size_t)NGn * 128];
__device__ __align__(16) float d_dx[(size_t)NDn * 128];
__device__ __align__(16) float d_g2[(size_t)NGn * 128];
__device__ __align__(16) float d_d2[(size_t)NDn * 128];
__device__ __align__(16) int   d_degcat[NT];
__device__ __align__(16) int   d_rowcat[NT + 1];
__device__ __align__(16) int   d_cursor[NT];
__device__ __align__(16) int   d_eidx[ETOT];
__device__ __align__(16) int   d_bsum[NBLK];
__device__ __align__(16) __nv_bfloat16 d_Bh[10 * CH];
__device__ __align__(16) __nv_bfloat16 d_Bl[10 * CH];
__device__ __align__(16) float d_Bf[10 * HH];
__device__ __align__(16) float d_cg[2 * 128];
__device__ __align__(16) float d_cd[2 * 128];
__device__ __align__(16) float d_bnacc[512];
__device__ __align__(16) float d_bnscale[256];
__device__ __align__(16) float d_bnshift[256];

// ---------------- ptx helpers ----------------
__device__ __forceinline__ uint32_t smem_u32(const void* p) {
    uint32_t a;
    asm("{ .reg .u64 t; cvta.to.shared.u64 t, %1; cvt.u32.u64 %0, t; }" : "=r"(a) : "l"(p));
    return a;
}
#if TC_OK
__device__ __forceinline__ uint32_t elect1() {
    uint32_t r;
    asm volatile("{ .reg .pred p; elect.sync _|p, 0xFFFFFFFF; selp.b32 %0, 1, 0, p; }" : "=r"(r));
    return r;
}
__device__ __forceinline__ uint64_t mk_desc(uint32_t addr) {
    const uint64_t base = (2ull << 61) | (1ull << 46) | (64ull << 32) | (1ull << 16);
    return base | ((uint64_t)(addr >> 4) & 0x3FFF);
}
__device__ __forceinline__ void mma_f16_ss(uint32_t d, uint64_t ad, uint64_t bd_, uint32_t idesc, bool acc) {
    uint32_t en = acc ? 1u : 0u, z = 0u;
    asm volatile(
        "{\n\t.reg .pred p;\n\tsetp.ne.u32 p, %5, 0;\n\t"
        "tcgen05.mma.cta_group::1.kind::f16 [%0], %1, %2, %3, {%4, %4, %4, %4}, p;\n\t}"
        :: "r"(d), "l"(ad), "l"(bd_), "r"(idesc), "r"(z), "r"(en) : "memory");
}
#define MBAR_WAIT(addr, ph) do {                                              \
    uint32_t _m = (addr), _p = (ph), _done;                                   \
    asm volatile("{\n\t.reg .pred p;\n\t"                                     \
        "mbarrier.try_wait.parity.acquire.cta.shared::cta.b64 p, [%1], %2;\n\t" \
        "selp.b32 %0, 1, 0, p;\n\t}" : "=r"(_done) : "r"(_m), "r"(_p) : "memory"); \
    if (!_done) {                                                             \
        asm volatile("{\n\t.reg .pred P1;\n\t"                                \
            "W%=:\n\tmbarrier.try_wait.parity.acquire.cta.shared::cta.b64 P1, [%0], %1, 0x989680;\n\t" \
            "@P1 bra.uni D%=;\n\tbra.uni W%=;\n\tD%=:\n\t}"                  \
            :: "r"(_m), "r"(_p) : "memory");                                  \
    } } while (0)

#define TC_LD_X32(r, a) asm volatile(                                         \
    "tcgen05.ld.sync.aligned.32x32b.x32.b32 "                                \
    "{%0, %1, %2, %3, %4, %5, %6, %7, %8, %9, %10, %11, %12, %13, %14, %15, "\
    " %16, %17, %18, %19, %20, %21, %22, %23, %24, %25, %26, %27, %28, %29, %30, %31}, [%32];" \
    : "=r"((r)[0]), "=r"((r)[1]), "=r"((r)[2]), "=r"((r)[3]),                 \
      "=r"((r)[4]), "=r"((r)[5]), "=r"((r)[6]), "=r"((r)[7]),                 \
      "=r"((r)[8]), "=r"((r)[9]), "=r"((r)[10]), "=r"((r)[11]),               \
      "=r"((r)[12]), "=r"((r)[13]), "=r"((r)[14]), "=r"((r)[15]),             \
      "=r"((r)[16]), "=r"((r)[17]), "=r"((r)[18]), "=r"((r)[19]),             \
      "=r"((r)[20]), "=r"((r)[21]), "=r"((r)[22]), "=r"((r)[23]),             \
      "=r"((r)[24]), "=r"((r)[25]), "=r"((r)[26]), "=r"((r)[27]),             \
      "=r"((r)[28]), "=r"((r)[29]), "=r"((r)[30]), "=r"((r)[31])              \
    : "r"(a))
#endif  // TC_OK

// ---------------- prep (also zeroes small scratch; ordered before consumers) ----------------
__global__ void prep_w3(const float* __restrict__ Wd1, const float* __restrict__ Ws1,
                        const float* __restrict__ Wu1, const float* __restrict__ Wd2,
                        const float* __restrict__ Ws2, const float* __restrict__ Wu2,
                        __nv_bfloat16* __restrict__ Bh, __nv_bfloat16* __restrict__ Bl,
                        float* __restrict__ Bf) {
    {
        int lb = (blockIdx.z * 5 + blockIdx.y) * 128 + blockIdx.x;
        int gtid = lb * 256 + threadIdx.x;
        int total = gridDim.x * gridDim.y * gridDim.z * 256;
        for (int k = gtid; k < NT; k += total) d_degcat[k] = 0;
        if (gtid < 512) d_bnacc[gtid] = 0.f;
        if (gtid < 256) d_cg[gtid] = 0.f;
    }
    __shared__ float red[2][128];
    int r = blockIdx.x, m = blockIdx.y, layer = blockIdx.z;
    int j = threadIdx.x & 127, kh = threadIdx.x >> 7;
    const float* Wd = layer ? Wd2 : Wd1;
    const float* Ws = layer ? Ws2 : Ws1;
    const float* Wu = layer ? Wu2 : Wu1;
    float acc = 0.f;
    int k0 = kh * 64, k1 = k0 + 64;
    if (m == 0) {
        for (int k = k0; k < k1; k++)
            acc += Wd[0 * HH + r * 128 + k] * Wu[0 * 2 * HH + k * 128 + j]
                 + Wd[2 * HH + r * 128 + k] * Wu[2 * 2 * HH + k * 128 + j];
    } else if (m == 1) {
        for (int k = k0; k < k1; k++)
            acc += Ws[0 * HH + r * 128 + k] * Wu[0 * 2 * HH + (128 + k) * 128 + j];
    } else if (m == 2) {
        for (int k = k0; k < k1; k++)
            acc += Ws[2 * HH + r * 128 + k] * Wu[2 * 2 * HH + (128 + k) * 128 + j];
    } else if (m == 3) {
        for (int k = k0; k < k1; k++)
            acc += Wd[1 * HH + r * 128 + k] * Wu[1 * 2 * HH + k * 128 + j];
    } else {
        for (int k = k0; k < k1; k++)
            acc += Ws[1 * HH + r * 128 + k] * Wu[1 * 2 * HH + (128 + k) * 128 + j];
    }
    red[kh][j] = acc;
    __syncthreads();
    if (kh == 0) {
        float v = red[0][j] + red[1][j];
        if (m < 3) v *= 0.5f;
        int cidx = layer * 5 + m;
        Bf[cidx * HH + r * 128 + j] = v;
        uint32_t byte = (uint32_t)j * 128 + (uint32_t)(r & 63) * 2;
        uint32_t swz = byte ^ ((byte >> 3) & 0x70);
        int idx = cidx * CH + (r >> 6) * 8192 + (int)(swz >> 1);
        __nv_bfloat16 h = __float2bfloat16(v);
        Bh[idx] = h;
        Bl[idx] = __float2bfloat16(v - __bfloat162float(h));
    }
}

__global__ void prep_bias3(const float* __restrict__ bd1, const float* __restrict__ bs1,
                           const float* __restrict__ bu1, const float* __restrict__ Wu1,
                           const float* __restrict__ bd2, const float* __restrict__ bs2,
                           const float* __restrict__ bu2, const float* __restrict__ Wu2) {
    __shared__ float red[4][128];
    int i = blockIdx.x, layer = blockIdx.y;
    int j = threadIdx.x & 127, kq = threadIdx.x >> 7;
    const float* bd = layer ? bd2 : bd1;
    const float* bs = layer ? bs2 : bs1;
    const float* bu = layer ? bu2 : bu1;
    const float* Wu = layer ? Wu2 : Wu1;
    float c = 0.f;
    for (int k = kq * 32; k < kq * 32 + 32; k++)
        c += bd[i * 128 + k] * Wu[i * 2 * HH + k * 128 + j]
           + bs[i * 128 + k] * Wu[i * 2 * HH + (128 + k) * 128 + j];
    red[kq][j] = c;
    __syncthreads();
    if (kq == 0) {
        float v = red[0][j] + red[1][j] + red[2][j] + red[3][j] + bu[i * 128 + j];
        if (i == 1) d_cd[layer * 128 + j] = v;
        else atomicAdd(&d_cg[layer * 128 + j], 0.5f * v);
    }
}

// ---------------- CSR build ----------------
__global__ void deg_all(const int* __restrict__ gg_dst, const int* __restrict__ gda_dst,
                        const int* __restrict__ gda_src) {
    int e = blockIdx.x * blockDim.x + threadIdx.x;
    if (e < EGG) atomicAdd(&d_degcat[gg_dst[e]], 1);
    else if (e < EGG + EGDA) atomicAdd(&d_degcat[NGn + gda_dst[e - EGG]], 1);
    else if (e < ETOT) atomicAdd(&d_degcat[NGn + NDn + gda_src[e - EGG - EGDA]], 1);
}
__global__ void scan1() {
    __shared__ int s[1024];
    int tid = threadIdx.x;
    int i = blockIdx.x * 1024 + tid;
    int v = (i < NT) ? d_degcat[i] : 0;
    s[tid] = v;
    __syncthreads();
    for (int off = 1; off < 1024; off <<= 1) {
        int t = (tid >= off) ? s[tid - off] : 0;
        __syncthreads();
        s[tid] += t;
        __syncthreads();
    }
    if (i < NT) d_rowcat[i] = s[tid] - v;
    if (tid == 1023) d_bsum[blockIdx.x] = s[1023];
}
__global__ void scan23() {
    __shared__ int s[128];
    int tid = threadIdx.x;
    if (tid < 128) s[tid] = (tid < NBLK && tid < blockIdx.x) ? d_bsum[tid] : 0;
    __syncthreads();
    for (int off = 64; off >= 1; off >>= 1) {
        if (tid < off) s[tid] += s[tid + off];
        __syncthreads();
    }
    int i = blockIdx.x * 1024 + tid;
    if (i < NT) {
        int r = d_rowcat[i] + s[0];
        d_rowcat[i] = r;
        d_cursor[i] = r;
    }
    if (blockIdx.x == 0 && tid == 0) d_rowcat[NT] = ETOT;
}
__global__ void fill_all(const int* __restrict__ gg_src, const int* __restrict__ gg_dst,
                         const int* __restrict__ gda_src, const int* __restrict__ gda_dst) {
    int e = blockIdx.x * blockDim.x + threadIdx.x;
    int v, slot;
    if (e < EGG) { v = gg_src[e]; slot = gg_dst[e]; }
    else if (e < EGG + EGDA) { int q = e - EGG; v = gda_src[q]; slot = NGn + gda_dst[q]; }
    else if (e < ETOT) { int q = e - EGG - EGDA; v = gda_dst[q]; slot = NGn + NDn + gda_src[q]; }
    else return;
    int pos = atomicAdd(&d_cursor[slot], 1);
    d_eidx[pos] = v;
}

// ---------------- persistent CSR mean-gather (warp grid-stride over slots) ----------------
__global__ void __launch_bounds__(256)
gather_all(const float* __restrict__ Xg, const float* __restrict__ Xd,
           const float* __restrict__ bnsc, const float* __restrict__ bnsh) {
    int lane = threadIdx.x & 31;
    int gwid = blockIdx.x * 8 + (threadIdx.x >> 5);
    const int nwarp = PBLK * 8;
    bool bn = (bnsc != nullptr);
#define BNT(v, scv, shv) do { if (bn) {                                        \
        v.x = v.x * scv.x + shv.x; v.x = v.x >= 0.f ? v.x : SLOPE * v.x;      \
        v.y = v.y * scv.y + shv.y; v.y = v.y >= 0.f ? v.y : SLOPE * v.y;      \
        v.z = v.z * scv.z + shv.z; v.z = v.z >= 0.f ? v.z : SLOPE * v.z;      \
        v.w = v.w * scv.w + shv.w; v.w = v.w >= 0.f ? v.w : SLOPE * v.w; } } while (0)
    for (int w = gwid; w < NT; w += nwarp) {
        const float* X;
        float* out;
        int grp;
        if (w < NGn) { X = Xg; out = d_agg_gg + (size_t)w * 128; grp = 0; }
        else if (w < NGn + NDn) { X = Xg; out = d_agg_gd + (size_t)(w - NGn) * 128; grp = 0; }
        else { X = Xd; out = d_agg_dg + (size_t)(w - NGn - NDn) * 128; grp = 1; }
        float4 scv = make_float4(1.f, 1.f, 1.f, 1.f), shv = make_float4(0.f, 0.f, 0.f, 0.f);
        if (bn) {
            scv = *(const float4*)(bnsc + grp * 128 + lane * 4);
            shv = *(const float4*)(bnsh + grp * 128 + lane * 4);
        }
        int start = __ldg(d_rowcat + w), end = __ldg(d_rowcat + w + 1);
        float4 a0 = make_float4(0.f, 0.f, 0.f, 0.f), a1 = a0, a2 = a0, a3 = a0;
        int e = start;
        int e4 = start + ((end - start) & ~3);
        for (; e < e4; e += 4) {
            int i0 = __ldg(d_eidx + e + 0);
            int i1 = __ldg(d_eidx + e + 1);
            int i2 = __ldg(d_eidx + e + 2);
            int i3 = __ldg(d_eidx + e + 3);
            float4 v0 = *(const float4*)(X + (size_t)i0 * 128 + lane * 4);
            float4 v1 = *(const float4*)(X + (size_t)i1 * 128 + lane * 4);
            float4 v2 = *(const float4*)(X + (size_t)i2 * 128 + lane * 4);
            float4 v3 = *(const float4*)(X + (size_t)i3 * 128 + lane * 4);
            BNT(v0, scv, shv); BNT(v1, scv, shv); BNT(v2, scv, shv); BNT(v3, scv, shv);
            a0.x += v0.x; a0.y += v0.y; a0.z += v0.z; a0.w += v0.w;
            a1.x += v1.x; a1.y += v1.y; a1.z += v1.z; a1.w += v1.w;
            a2.x += v2.x; a2.y += v2.y; a2.z += v2.z; a2.w += v2.w;
            a3.x += v3.x; a3.y += v3.y; a3.z += v3.z; a3.w += v3.w;
        }
        for (; e < end; e++) {
            int i0 = __ldg(d_eidx + e);
            float4 v0 = *(const float4*)(X + (size_t)i0 * 128 + lane * 4);
            BNT(v0, scv, shv);
            a0.x += v0.x; a0.y += v0.y; a0.z += v0.z; a0.w += v0.w;
        }
        float inv = 1.0f / fmaxf((float)(end - start), 1.0f);
        float4 acc;
        acc.x = (a0.x + a1.x + a2.x + a3.x) * inv;
        acc.y = (a0.y + a1.y + a2.y + a3.y) * inv;
        acc.z = (a0.z + a1.z + a2.z + a3.z) * inv;
        acc.w = (a0.w + a1.w + a2.w + a3.w) * inv;
        *(float4*)(out + lane * 4) = acc;
    }
#undef BNT
}

// ---------------- tcgen05 split-bf16 GEMM, k=64 panels, 3 CTAs/SM ----------------
__global__ void __launch_bounds__(256, 3)
gemm_tc_all(float* __restrict__ outG, float* __restrict__ outD,
            const float* __restrict__ gA0, const float* __restrict__ gA1,
            const float* __restrict__ gA2,
            const float* __restrict__ dA0, const float* __restrict__ dA1,
            const __nv_bfloat16* __restrict__ Bh, const __nv_bfloat16* __restrict__ Bl,
            const float* __restrict__ biasG, const float* __restrict__ biasD,
            const float* __restrict__ bnsc, const float* __restrict__ bnsh) {
#if TC_OK
    extern __shared__ __align__(16) char smem[];
    uint32_t raw = smem_u32(smem);
    uint32_t sb = (raw + 1023u) & ~1023u;
    char* sp = (char*)smem + (sb - raw);
    const uint32_t OAH = 1024, OAL = OAH + 16384, OBH = OAL + 16384, OBL = OBH + 16384;
    int tid = threadIdx.x, wid = tid >> 5, lane = tid & 31;

    bool gene = (blockIdx.x < GBg);
    int m0 = (gene ? blockIdx.x : blockIdx.x - GBg) * 128;
    int M = gene ? NGn : NDn;
    int nchunks = gene ? 3 : 2;
    float* out = gene ? outG : outD;
    const float* bias = gene ? biasG : biasD;
    const __nv_bfloat16* BhB = Bh + (gene ? 0 : 3) * (size_t)CH;
    const __nv_bfloat16* BlB = Bl + (gene ? 0 : 3) * (size_t)CH;
    int grp = gene ? 0 : 1;

    if (wid == 0)
        asm volatile("tcgen05.alloc.cta_group::1.sync.aligned.shared::cta.b32 [%0], %1;"
                     :: "r"(sb), "r"(128) : "memory");
    if (tid == 0)
        asm volatile("mbarrier.init.shared.b64 [%0], %1;" :: "r"(sb + 8), "r"(1) : "memory");
    __syncthreads();
    uint32_t tmem;
    asm volatile("ld.shared.b32 %0, [%1];" : "=r"(tmem) : "r"(sb));
    const uint32_t idesc = 0x08200490u;

    int it = 0;
    for (int c = 0; c < nchunks; c++) {
        const float* A = gene ? ((c == 0) ? gA0 : ((c == 1) ? gA1 : gA2))
                              : ((c == 0) ? dA0 : dA1);
        bool dobn = (c == 0) && (bnsc != nullptr);
        for (int p = 0; p < 2; p++) {
            for (int i = tid; i < 2048; i += 256) {
                int row = i >> 4;
                int kq = (i & 15) << 2;
                int k4 = p * 64 + kq;
                float4 v = make_float4(0.f, 0.f, 0.f, 0.f);
                int gm = m0 + row;
                if (gm < M) {
                    v = *(const float4*)(A + (size_t)gm * 128 + k4);
                    if (dobn) {
                        float4 sc = *(const float4*)(bnsc + grp * 128 + k4);
                        float4 sh = *(const float4*)(bnsh + grp * 128 + k4);
                        v.x = v.x * sc.x + sh.x; v.x = v.x >= 0.f ? v.x : SLOPE * v.x;
                        v.y = v.y * sc.y + sh.y; v.y = v.y >= 0.f ? v.y : SLOPE * v.y;
                        v.z = v.z * sc.z + sh.z; v.z = v.z >= 0.f ? v.z : SLOPE * v.z;
                        v.w = v.w * sc.w + sh.w; v.w = v.w >= 0.f ? v.w : SLOPE * v.w;
                    }
                }
                __nv_bfloat162 h0 = __float22bfloat162_rn(make_float2(v.x, v.y));
                __nv_bfloat162 h1 = __float22bfloat162_rn(make_float2(v.z, v.w));
                float2 f0 = __bfloat1622float2(h0), f1 = __bfloat1622float2(h1);
                __nv_bfloat162 l0 = __float22bfloat162_rn(make_float2(v.x - f0.x, v.y - f0.y));
                __nv_bfloat162 l1 = __float22bfloat162_rn(make_float2(v.z - f1.x, v.w - f1.y));
                uint32_t byte = (uint32_t)row * 128 + (uint32_t)kq * 2;
                uint32_t swz = byte ^ ((byte >> 3) & 0x70);
                *(uint2*)(sp + OAH + swz) = make_uint2(*(uint32_t*)&h0, *(uint32_t*)&h1);
                *(uint2*)(sp + OAL + swz) = make_uint2(*(uint32_t*)&l0, *(uint32_t*)&l1);
            }
            for (int i = tid; i < 1024; i += 256) {
                ((float4*)(sp + OBH))[i] = ((const float4*)(BhB + (size_t)c * CH + p * 8192))[i];
                ((float4*)(sp + OBL))[i] = ((const float4*)(BlB + (size_t)c * CH + p * 8192))[i];
            }
            asm volatile("fence.proxy.async.shared::cta;" ::: "memory");
            __syncthreads();

            if (wid == 0 && elect1()) {
                for (int t = 0; t < 3; t++) {
                    uint32_t aoff = (t == 1) ? OAL : OAH;
                    uint32_t boff = (t == 2) ? OBL : OBH;
                    uint64_t ad  = mk_desc(sb + aoff);
                    uint64_t bd_ = mk_desc(sb + boff);
                    for (int s = 0; s < 4; s++)
                        mma_f16_ss(tmem, ad + s * 2, bd_ + s * 2, idesc,
                                   !(it == 0 && t == 0 && s == 0));
                }
                asm volatile("tcgen05.commit.cta_group::1.mbarrier::arrive::one.shared::cluster.b64 [%0];"
                             :: "r"(sb + 8) : "memory");
            }
            MBAR_WAIT(sb + 8, (uint32_t)(it & 1));
            __syncthreads();
            it++;
        }
    }
    asm volatile("tcgen05.fence::after_thread_sync;" ::: "memory");

    if (wid < 4) {
        int gm = m0 + wid * 32 + lane;
        for (int b = 0; b < 4; b++) {
            uint32_t r[32];
            TC_LD_X32(r, tmem + b * 32);
            asm volatile("tcgen05.wait::ld.sync.aligned;" ::: "memory");
            if (gm < M) {
#pragma unroll
                for (int q = 0; q < 8; q++) {
                    float4 o;
                    o.x = __uint_as_float(r[q * 4 + 0]) + __ldg(bias + b * 32 + q * 4 + 0);
                    o.y = __uint_as_float(r[q * 4 + 1]) + __ldg(bias + b * 32 + q * 4 + 1);
                    o.z = __uint_as_float(r[q * 4 + 2]) + __ldg(bias + b * 32 + q * 4 + 2);
                    o.w = __uint_as_float(r[q * 4 + 3]) + __ldg(bias + b * 32 + q * 4 + 3);
                    *(float4*)(out + (size_t)gm * 128 + b * 32 + q * 4) = o;
                }
            }
        }
    }
    __syncthreads();
    if (tid == 0)
        asm volatile("mbarrier.inval.shared.b64 [%0];" :: "r"(sb + 8) : "memory");
    __syncthreads();
    if (wid == 0) {
        asm volatile("tcgen05.relinquish_alloc_permit.cta_group::1.sync.aligned;");
        asm volatile("tcgen05.dealloc.cta_group::1.sync.aligned.b32 %0, %1;" :: "r"(tmem), "r"(128));
    }
#endif  // TC_OK
}

// ---------------- SIMT fallback (base-arch cubin only) ----------------
__global__ void __launch_bounds__(256, 2)
gemm_simt_all(float* __restrict__ outG, float* __restrict__ outD,
              const float* __restrict__ gA0, const float* __restrict__ gA1,
              const float* __restrict__ gA2,
              const float* __restrict__ dA0, const float* __restrict__ dA1,
              const float* __restrict__ Bf,
              const float* __restrict__ biasG, const float* __restrict__ biasD,
              const float* __restrict__ bnsc, const float* __restrict__ bnsh) {
#if !TC_OK
    __shared__ float As[16][128];
    __shared__ float Bs[16][128];
    int tid = threadIdx.x;
    int tx = tid & 15, ty = tid >> 4;
    bool gene = (blockIdx.x < GBg);
    int m0 = (gene ? blockIdx.x : blockIdx.x - GBg) * 128;
    int M = gene ? NGn : NDn;
    int nchunks = gene ? 3 : 2;
    float* out = gene ? outG : outD;
    const float* bias = gene ? biasG : biasD;
    const float* B = Bf + (gene ? 0 : 3) * (size_t)HH;
    int grp = gene ? 0 : 1;
    float acc[8][8];
#pragma unroll
    for (int i = 0; i < 8; i++)
#pragma unroll
        for (int j = 0; j < 8; j++) acc[i][j] = 0.f;

    for (int c = 0; c < nchunks; c++) {
        const float* A = gene ? ((c == 0) ? gA0 : (c == 1) ? gA1 : gA2)
                              : ((c == 0) ? dA0 : dA1);
        bool dobn = (c == 0) && (bnsc != nullptr);
        const float* Bc = B + (size_t)c * HH;
        for (int k0 = 0; k0 < 128; k0 += 16) {
#pragma unroll
            for (int f = 0; f < 2; f++) {
                int lin = tid * 2 + f;
                int row = lin >> 2;
                int kk = (lin & 3) << 2;
                float4 v = make_float4(0.f, 0.f, 0.f, 0.f);
                int gm = m0 + row;
                if (gm < M) {
                    v = *(const float4*)(A + (size_t)gm * 128 + k0 + kk);
                    if (dobn) {
                        float4 sc = *(const float4*)(bnsc + grp * 128 + k0 + kk);
                        float4 sh = *(const float4*)(bnsh + grp * 128 + k0 + kk);
                        v.x = v.x * sc.x + sh.x; v.x = v.x >= 0.f ? v.x : SLOPE * v.x;
                        v.y = v.y * sc.y + sh.y; v.y = v.y >= 0.f ? v.y : SLOPE * v.y;
                        v.z = v.z * sc.z + sh.z; v.z = v.z >= 0.f ? v.z : SLOPE * v.z;
                        v.w = v.w * sc.w + sh.w; v.w = v.w >= 0.f ? v.w : SLOPE * v.w;
                    }
                }
                As[kk + 0][row] = v.x; As[kk + 1][row] = v.y;
                As[kk + 2][row] = v.z; As[kk + 3][row] = v.w;
                int kb = lin >> 5;
                int jb = (lin & 31) << 2;
                *(float4*)&Bs[kb][jb] = *(const float4*)(Bc + (size_t)(k0 + kb) * 128 + jb);
            }
            __syncthreads();
#pragma unroll
            for (int kk = 0; kk < 16; kk++) {
                float a[8], b[8];
#pragma unroll
                for (int i = 0; i < 8; i++) a[i] = As[kk][ty * 8 + i];
#pragma unroll
                for (int j = 0; j < 8; j++) b[j] = Bs[kk][tx * 8 + j];
#pragma unroll
                for (int i = 0; i < 8; i++)
#pragma unroll
                    for (int j = 0; j < 8; j++) acc[i][j] = fmaf(a[i], b[j], acc[i][j]);
            }
            __syncthreads();
        }
    }
    float bb[8];
#pragma unroll
    for (int j = 0; j < 8; j++) bb[j] = bias[tx * 8 + j];
#pragma unroll
    for (int i = 0; i < 8; i++) {
        int gm = m0 + ty * 8 + i;
        if (gm < M) {
#pragma unroll
            for (int j = 0; j < 8; j += 4)
                *(float4*)(out + (size_t)gm * 128 + tx * 8 + j) =
                    make_float4(acc[i][j] + bb[j], acc[i][j + 1] + bb[j + 1],
                                acc[i][j + 2] + bb[j + 2], acc[i][j + 3] + bb[j + 3]);
        }
    }
#endif  // !TC_OK
}

// ---------------- BN ----------------
__global__ void bn_stats_all() {
    __shared__ float4 s_s[8][32], s_q[8][32];
    int tid = threadIdx.x, w = tid >> 5, l = tid & 31;
    const float* X;
    float* acc;
    int M, bb, nb;
    if (blockIdx.x < 256) { X = d_gx; acc = d_bnacc; M = NGn; bb = blockIdx.x; nb = 256; }
    else { X = d_dx; acc = d_bnacc + 256; M = NDn; bb = blockIdx.x - 256; nb = 128; }
    float4 s = make_float4(0.f, 0.f, 0.f, 0.f), q = s;
    for (int r = bb * 8 + w; r < M; r += nb * 8) {
        float4 v = ((const float4*)X)[(size_t)r * 32 + l];
        s.x += v.x; s.y += v.y; s.z += v.z; s.w += v.w;
        q.x += v.x * v.x; q.y += v.y * v.y; q.z += v.z * v.z; q.w += v.w * v.w;
    }
    s_s[w][l] = s; s_q[w][l] = q;
    __syncthreads();
    if (w == 0) {
        float4 ts = s_s[0][l], tq = s_q[0][l];
        for (int ww = 1; ww < 8; ww++) {
            float4 a = s_s[ww][l], b = s_q[ww][l];
            ts.x += a.x; ts.y += a.y; ts.z += a.z; ts.w += a.w;
            tq.x += b.x; tq.y += b.y; tq.z += b.z; tq.w += b.w;
        }
        atomicAdd(&acc[l * 4 + 0], ts.x); atomicAdd(&acc[l * 4 + 1], ts.y);
        atomicAdd(&acc[l * 4 + 2], ts.z); atomicAdd(&acc[l * 4 + 3], ts.w);
        atomicAdd(&acc[128 + l * 4 + 0], tq.x); atomicAdd(&acc[128 + l * 4 + 1], tq.y);
        atomicAdd(&acc[128 + l * 4 + 2], tq.z); atomicAdd(&acc[128 + l * 4 + 3], tq.w);
    }
}
__global__ void bn_finalize(const float* __restrict__ gamma, const float* __restrict__ beta) {
    int t = threadIdx.x;
    int grp = t >> 7, j = t & 127;
    float cnt = grp ? (float)NDn : (float)NGn;
    float mean = d_bnacc[grp * 256 + j] / cnt;
    float var = d_bnacc[grp * 256 + 128 + j] / cnt - mean * mean;
    float sc = gamma[grp * 128 + j] * rsqrtf(var + EPSBN);
    d_bnscale[grp * 128 + j] = sc;
    d_bnshift[grp * 128 + j] = beta[grp * 128 + j] - mean * sc;
}

// ---------------- persistent decoder ----------------
__global__ void __launch_bounds__(256)
decoder(const int* __restrict__ ls, const int* __restrict__ ld,
        float* __restrict__ out) {
    int lane = threadIdx.x & 31;
    int gwid = blockIdx.x * 8 + (threadIdx.x >> 5);
    const int nwarp = PBLK * 8;
    for (int w = gwid; w < ELAB; w += nwarp) {
        int s = __ldg(ls + w), t = __ldg(ld + w);
        float4 a = *(const float4*)(d_g2 + (size_t)s * 128 + lane * 4);
        float4 b = *(const float4*)(d_d2 + (size_t)t * 128 + lane * 4);
        float p = a.x * b.x + a.y * b.y + a.z * b.z + a.w * b.w;
#pragma unroll
        for (int o = 16; o; o >>= 1) p += __shfl_xor_sync(0xffffffffu, p, o);
        if (lane == 0) out[w] = p;
    }
}

// ---------------- host ----------------
extern "C" void kernel_launch(void* const* d_in, const int* in_sizes, int n_in,
                              void* d_out, int out_size) {
    const float* x_gene = (const float*)d_in[0];
    const float* x_dis  = (const float*)d_in[1];
    const float* Wd1 = (const float*)d_in[2];
    const float* Ws1 = (const float*)d_in[3];
    const float* Wu1 = (const float*)d_in[4];
    const float* bd1 = (const float*)d_in[5];
    const float* bs1 = (const float*)d_in[6];
    const float* bu1 = (const float*)d_in[7];
    const float* Wd2 = (const float*)d_in[8];
    const float* Ws2 = (const float*)d_in[9];
    const float* Wu2 = (const float*)d_in[10];
    const float* bd2 = (const float*)d_in[11];
    const float* bs2 = (const float*)d_in[12];
    const float* bu2 = (const float*)d_in[13];
    const float* gamma = (const float*)d_in[14];
    const float* beta  = (const float*)d_in[15];
    const int* gg_src = (const int*)d_in[16];
    const int* gg_dst = (const int*)d_in[17];
    const int* gda_src = (const int*)d_in[18];
    const int* gda_dst = (const int*)d_in[19];
    const int* ls = (const int*)d_in[20];
    const int* ld = (const int*)d_in[21];
    float* out = (float*)d_out;

    float *p_agg_gg, *p_agg_dg, *p_agg_gd, *p_gx, *p_dx, *p_g2, *p_d2;
    float *p_cg, *p_cd, *pBf, *p_bnsc, *p_bnsh;
    __nv_bfloat16 *pBh, *pBl;
    cudaGetSymbolAddress((void**)&p_agg_gg, d_agg_gg);
    cudaGetSymbolAddress((void**)&p_agg_dg, d_agg_dg);
    cudaGetSymbolAddress((void**)&p_agg_gd, d_agg_gd);
    cudaGetSymbolAddress((void**)&p_gx, d_gx);
    cudaGetSymbolAddress((void**)&p_dx, d_dx);
    cudaGetSymbolAddress((void**)&p_g2, d_g2);
    cudaGetSymbolAddress((void**)&p_d2, d_d2);
    cudaGetSymbolAddress((void**)&p_cg, d_cg);
    cudaGetSymbolAddress((void**)&p_cd, d_cd);
    cudaGetSymbolAddress((void**)&pBh, d_Bh);
    cudaGetSymbolAddress((void**)&pBl, d_Bl);
    cudaGetSymbolAddress((void**)&pBf, d_Bf);
    cudaGetSymbolAddress((void**)&p_bnsc, d_bnscale);
    cudaGetSymbolAddress((void**)&p_bnsh, d_bnshift);

    cudaFuncSetAttribute(gemm_tc_all, cudaFuncAttributeMaxDynamicSharedMemorySize, GEMM_SMEM);

    // prep (includes scratch zeroing)
    prep_w3<<<dim3(128, 5, 2), 256>>>(Wd1, Ws1, Wu1, Wd2, Ws2, Wu2, pBh, pBl, pBf);
    prep_bias3<<<dim3(3, 2), 512>>>(bd1, bs1, bu1, Wu1, bd2, bs2, bu2, Wu2);

    // CSR build
    deg_all<<<(ETOT + 255) / 256, 256>>>(gg_dst, gda_dst, gda_src);
    scan1<<<NBLK, 1024>>>();
    scan23<<<NBLK, 1024>>>();
    fill_all<<<(ETOT + 255) / 256, 256>>>(gg_src, gg_dst, gda_src, gda_dst);

    const int gemm_blocks = GBg + GBd;         // 548

    // ---- layer 1 ----
    gather_all<<<PBLK, 256>>>(x_gene, x_dis, nullptr, nullptr);
    gemm_tc_all<<<gemm_blocks, 256, GEMM_SMEM>>>(p_gx, p_dx, x_gene, p_agg_gg, p_agg_dg,
                                                 x_dis, p_agg_gd, pBh, pBl,
                                                 p_cg, p_cd, nullptr, nullptr);
    gemm_simt_all<<<gemm_blocks, 256>>>(p_gx, p_dx, x_gene, p_agg_gg, p_agg_dg,
                                        x_dis, p_agg_gd, pBf, p_cg, p_cd, nullptr, nullptr);
    bn_stats_all<<<384, 256>>>();
    bn_finalize<<<1, 256>>>(gamma, beta);

    // ---- layer 2 (bn+lrelu applied on the fly) ----
    gather_all<<<PBLK, 256>>>(p_gx, p_dx, p_bnsc, p_bnsh);
    gemm_tc_all<<<gemm_blocks, 256, GEMM_SMEM>>>(p_g2, p_d2, p_gx, p_agg_gg, p_agg_dg,
                                                 p_dx, p_agg_gd, pBh + 5 * CH, pBl + 5 * CH,
                                                 p_cg + 128, p_cd + 128, p_bnsc, p_bnsh);
    gemm_simt_all<<<gemm_blocks, 256>>>(p_g2, p_d2, p_gx, p_agg_gg, p_agg_dg,
                                        p_dx, p_agg_gd, pBf + 5 * HH,
                                        p_cg + 128, p_cd + 128, p_bnsc, p_bnsh);

    // ---- decoder ----
    decoder<<<PBLK, 256>>>(ls, ld, out);
}